// round 13
// baseline (speedup 1.0000x reference)
#include <cuda_runtime.h>
#include <cstdint>

#define BSZ   128
#define SEQ   256
#define FDIM  512
#define EDIM  512
#define HEADS 8
#define BSROWS (BSZ*SEQ)
#define MLPD  2048
#define MIN_POS 1e-6f

__device__ float g_xn  [(size_t)BSROWS*FDIM];
__device__ float g_xe  [(size_t)BSROWS*EDIM];
__device__ float g_hT  [(size_t)BSROWS*EDIM];   // hT [b,e,o] (tf32-rounded state)
__device__ float g_u1T [(size_t)BSROWS*EDIM];   // u1T[b,e,i] (tf32-rounded)
__device__ float g_r   [(size_t)BSROWS*EDIM];
__device__ float g_xres[(size_t)BSROWS*FDIM];
__device__ float g_mlp [(size_t)BSROWS*MLPD];
__device__ float g_gwT [(size_t)SEQ*SEQ];
__device__ float g_gwR [(size_t)SEQ*SEQ];
__device__ float g_ewR [(size_t)EDIM*FDIM];
__device__ float g_owR [(size_t)FDIM*EDIM];
__device__ float g_w1R [(size_t)MLPD*FDIM];
__device__ float g_w2R [(size_t)FDIM*MLPD];

// ---------------- helpers -----------------------------------------------------
__device__ __forceinline__ float rtf(float x) {
    uint32_t u;
    asm("cvt.rna.tf32.f32 %0, %1;" : "=r"(u) : "f"(x));
    return __uint_as_float(u);
}
#define CP16(dst, src) \
    asm volatile("cp.async.cg.shared.global [%0], [%1], 16;" :: "r"(dst), "l"(src))
#define CP_COMMIT() asm volatile("cp.async.commit_group;" ::: "memory")
#define CP_WAIT(n)  asm volatile("cp.async.wait_group %0;" :: "n"(n) : "memory")
#define L2PF(p) asm volatile("prefetch.global.L2 [%0];" :: "l"(p))
#define LDSM4(r0, r1, r2, r3, addr) \
    asm volatile("ldmatrix.sync.aligned.m8n8.x4.shared.b16 {%0,%1,%2,%3}, [%4];" \
                 : "=r"(r0), "=r"(r1), "=r"(r2), "=r"(r3) : "r"(addr))
__device__ __forceinline__ uint32_t s2u(const void* p) {
    uint32_t a;
    asm("{ .reg .u64 t; cvta.to.shared.u64 t, %1; cvt.u32.u64 %0, t; }" : "=r"(a) : "l"(p));
    return a;
}
__device__ __forceinline__ void mma_tf32(float* c, const uint32_t* a, const uint32_t* b) {
    asm volatile(
        "mma.sync.aligned.m16n8k8.row.col.f32.tf32.tf32.f32 "
        "{%0,%1,%2,%3}, {%4,%5,%6,%7}, {%8,%9}, {%0,%1,%2,%3};"
        : "+f"(c[0]), "+f"(c[1]), "+f"(c[2]), "+f"(c[3])
        : "r"(a[0]), "r"(a[1]), "r"(a[2]), "r"(a[3]), "r"(b[0]), "r"(b[1]));
}
static __device__ __forceinline__ float gelu_tanh(float v) {
    float t = tanhf(0.7978845608028654f * (v + 0.044715f * v * v * v));
    return 0.5f * v * (1.f + t);
}

// ---------------- tf32 mma GEMM: C[M,N]=A[M,K]@B[N,K]^T ----------------------
// 128x128 tile, 512 threads (4x4 warps, 32x32 warp tile), K-chunk 32,
// 3-stage cp.async ring, ldmatrix fragment loads.
// EPI: 0=bias+clip+L1norm64  1=bias+res  2=bias+gelu(round)  3=plain
//      4=fused NNMF-B in-place on hT   5=fused NNMF-A   6=NNMF-A last iter
#define SMP 36
#define STG (128*SMP)
#define MM_SMEM (6*STG*4)     // 110592 B

template <int EPI>
__global__ __launch_bounds__(512, 2) void mma_gemm(
    const float* __restrict__ A, const float* __restrict__ B,
    const float* __restrict__ bias, const float* __restrict__ res,
    float* __restrict__ C, float* __restrict__ aux, int K, int N,
    long long sB, long long sC)
{
    extern __shared__ float sm[];
    const int tid = threadIdx.x, wid = tid >> 5, lane = tid & 31;
    const int grp = lane >> 2, qid = lane & 3;
    const int n0 = blockIdx.x * 128;
    const size_t m0 = (size_t)blockIdx.y * 128;
    B += (size_t)blockIdx.z * sB;
    C += (size_t)blockIdx.z * sC;
    if (EPI == 1 || EPI == 4 || EPI == 5) res += (size_t)blockIdx.z * sC;
    if (EPI == 4 || EPI == 5) aux += (size_t)blockIdx.z * sC;
    const int wm = (wid & 3) * 32, wn = (wid >> 2) * 32;
    const uint32_t sAu = s2u(sm);

    const int t8 = lane >> 3, r8 = lane & 7;
    const int rowA = wm + (t8 & 1) * 8 + r8;
    const int colA = (t8 >> 1) * 4;
    const int rowB = wn + (t8 >> 1) * 8 + r8;
    const int colB = (t8 & 1) * 4;

    auto load_chunk = [&](int st, int kt) {
        uint32_t base = sAu + (uint32_t)(st * 2 * STG) * 4;
#pragma unroll
        for (int i = 0; i < 2; i++) {
            int id = tid + 512 * i;
            int row = id >> 3, kq = (id & 7) * 4;
            CP16(base + (uint32_t)(row * SMP + kq) * 4, &A[(m0 + row) * K + kt + kq]);
        }
        base += STG * 4;
#pragma unroll
        for (int i = 0; i < 2; i++) {
            int id = tid + 512 * i;
            int row = id >> 3, kq = (id & 7) * 4;
            CP16(base + (uint32_t)(row * SMP + kq) * 4, &B[(size_t)(n0 + row) * K + kt + kq]);
        }
        CP_COMMIT();
    };

    float cfr[2][4][4];
#pragma unroll
    for (int mt = 0; mt < 2; mt++)
#pragma unroll
        for (int nt = 0; nt < 4; nt++)
#pragma unroll
            for (int i = 0; i < 4; i++) cfr[mt][nt][i] = 0.f;

    const int nch = K >> 5;
    load_chunk(0, 0);
    if (nch > 1) load_chunk(1, 32);

    if (EPI == 5) {
        int row = tid >> 2, l = tid & 3;
        L2PF(&res[(m0 + row) * (size_t)N + n0 + l * 32]);
        if (tid < 128) L2PF(&bias[tid * 32]);
    } else if (EPI == 4) {
        int col = tid >> 2, l = tid & 3;
        L2PF(&res[(size_t)(n0 + col) * 256 + m0 + l * 32]);
    }

    for (int c = 0; c < nch; c++) {
        if (c + 1 < nch) CP_WAIT(1);
        else             CP_WAIT(0);
        __syncthreads();
        if (c + 2 < nch) load_chunk((c + 2) % 3, (c + 2) * 32);
        const uint32_t sAs = sAu + (uint32_t)((c % 3) * 2 * STG) * 4;
        const uint32_t sBs = sAs + STG * 4;
#pragma unroll
        for (int kk = 0; kk < 32; kk += 8) {
            uint32_t af[2][4], bf[2][4];
#pragma unroll
            for (int mt = 0; mt < 2; mt++)
                LDSM4(af[mt][0], af[mt][1], af[mt][2], af[mt][3],
                      sAs + (uint32_t)((rowA + mt * 16) * SMP + kk + colA) * 4);
#pragma unroll
            for (int ntp = 0; ntp < 2; ntp++)
                LDSM4(bf[ntp][0], bf[ntp][1], bf[ntp][2], bf[ntp][3],
                      sBs + (uint32_t)((rowB + ntp * 16) * SMP + kk + colB) * 4);
#pragma unroll
            for (int mt = 0; mt < 2; mt++)
#pragma unroll
                for (int nt = 0; nt < 4; nt++)
                    mma_tf32(cfr[mt][nt], af[mt], &bf[nt >> 1][(nt & 1) * 2]);
        }
    }
    __syncthreads();

    if (EPI == 5 || EPI == 6) {
        float* t1s = sm;             // [128][132]
        float* lwT = sm + 16896;     // [64][68]
        float* lwS = sm + 21248;     // [64][68]
        const uint32_t sT = sAu, sL1 = s2u(lwT), sL2 = s2u(lwS);
#pragma unroll
        for (int q = 0; q < 8; q++) {
            int idx = q * 512 + tid;
            int g = idx >> 6, f = idx & 63;
            float v = rtf(bias[idx]);
            lwT[f * 68 + g] = v;
            lwS[g * 68 + f] = v;
        }
#pragma unroll
        for (int mt = 0; mt < 2; mt++) {
            const int row = wm + mt * 16 + grp;
#pragma unroll
            for (int nt = 0; nt < 4; nt++) {
                const int col = wn + nt * 8 + qid * 2;
                t1s[row * 132 + col]           = rtf(cfr[mt][nt][0]);
                t1s[row * 132 + col + 1]       = rtf(cfr[mt][nt][1]);
                t1s[(row + 8) * 132 + col]     = rtf(cfr[mt][nt][2]);
                t1s[(row + 8) * 132 + col + 1] = rtf(cfr[mt][nt][3]);
            }
        }
        __syncthreads();

        // warps 0-7: hp=0 (cols 0-63); warps 8-15: hp=1 (cols 64-127)
        const int hp = wid >> 3, wm16 = (wid & 7) * 16;
        const uint32_t aB = sT + (uint32_t)((wm16 + (t8 & 1) * 8 + r8) * 132 + (t8 >> 1) * 4 + hp * 64) * 4;
        const int bRow2 = (t8 >> 1) * 8 + r8, bCol2 = (t8 & 1) * 4;

        float rc[8][4];
#pragma unroll
        for (int nt = 0; nt < 8; nt++)
#pragma unroll
            for (int j = 0; j < 4; j++) rc[nt][j] = 0.f;
#pragma unroll
        for (int kk = 0; kk < 64; kk += 8) {
            uint32_t af[4], bf[4][4];
            LDSM4(af[0], af[1], af[2], af[3], aB + (uint32_t)kk * 4);
#pragma unroll
            for (int n2 = 0; n2 < 4; n2++)
                LDSM4(bf[n2][0], bf[n2][1], bf[n2][2], bf[n2][3],
                      sL1 + (uint32_t)((n2 * 16 + bRow2) * 68 + kk + bCol2) * 4);
#pragma unroll
            for (int nt = 0; nt < 8; nt++)
                mma_tf32(rc[nt], af, &bf[nt >> 1][(nt & 1) * 2]);
        }
        float s0 = 0.f, s1 = 0.f;
#pragma unroll
        for (int nt = 0; nt < 8; nt++) {
#pragma unroll
            for (int j = 0; j < 4; j++) rc[nt][j] = fmaxf(rc[nt][j], MIN_POS);
            s0 += rc[nt][0] + rc[nt][1];
            s1 += rc[nt][2] + rc[nt][3];
        }
        s0 += __shfl_xor_sync(0xffffffffu, s0, 1);
        s0 += __shfl_xor_sync(0xffffffffu, s0, 2);
        s1 += __shfl_xor_sync(0xffffffffu, s1, 1);
        s1 += __shfl_xor_sync(0xffffffffu, s1, 2);

        const size_t ra = (m0 + wm16 + grp) * (size_t)N + n0 + hp * 64;
        const size_t rb = ra + 8 * (size_t)N;

        if (EPI == 6) {
            const float inv0 = 1.f / s0, inv1 = 1.f / s1;
#pragma unroll
            for (int nt = 0; nt < 8; nt++) {
                const int f = nt * 8 + qid * 2;
                float2 rv0; rv0.x = rtf(rc[nt][0] * inv0); rv0.y = rtf(rc[nt][1] * inv0);
                float2 rv1; rv1.x = rtf(rc[nt][2] * inv1); rv1.y = rtf(rc[nt][3] * inv1);
                *(float2*)&C[ra + f] = rv0;
                *(float2*)&C[rb + f] = rv1;
            }
            return;
        }

        // xr = xe*s/rc -> t1s (disjoint per-warp region: rows wm16.., cols hp*64..)
#pragma unroll
        for (int nt = 0; nt < 8; nt++) {
            const int f = nt * 8 + qid * 2;
            float2 x0 = *(const float2*)&res[ra + f];
            float2 x1 = *(const float2*)&res[rb + f];
            t1s[(wm16 + grp) * 132 + hp * 64 + f]         = rtf(x0.x * s0 / rc[nt][0]);
            t1s[(wm16 + grp) * 132 + hp * 64 + f + 1]     = rtf(x0.y * s0 / rc[nt][1]);
            t1s[(wm16 + grp + 8) * 132 + hp * 64 + f]     = rtf(x1.x * s1 / rc[nt][2]);
            t1s[(wm16 + grp + 8) * 132 + hp * 64 + f + 1] = rtf(x1.y * s1 / rc[nt][3]);
        }
        __syncwarp();

        float uu[8][4];
#pragma unroll
        for (int nt = 0; nt < 8; nt++)
#pragma unroll
            for (int j = 0; j < 4; j++) uu[nt][j] = 0.f;
#pragma unroll
        for (int kk = 0; kk < 64; kk += 8) {
            uint32_t af[4], bf[4][4];
            LDSM4(af[0], af[1], af[2], af[3], aB + (uint32_t)kk * 4);
#pragma unroll
            for (int n2 = 0; n2 < 4; n2++)
                LDSM4(bf[n2][0], bf[n2][1], bf[n2][2], bf[n2][3],
                      sL2 + (uint32_t)((n2 * 16 + bRow2) * 68 + kk + bCol2) * 4);
#pragma unroll
            for (int nt = 0; nt < 8; nt++)
                mma_tf32(uu[nt], af, &bf[nt >> 1][(nt & 1) * 2]);
        }
        {
            const size_t eb = (size_t)(n0 + hp * 64) * 256 + m0;
            const int i = wm16 + grp;
#pragma unroll
            for (int nt = 0; nt < 8; nt++) {
                const int g = nt * 8 + qid * 2;
                aux[eb + (size_t)g * 256 + i]           = rtf(uu[nt][0]);
                aux[eb + (size_t)(g + 1) * 256 + i]     = rtf(uu[nt][1]);
                aux[eb + (size_t)g * 256 + i + 8]       = rtf(uu[nt][2]);
                aux[eb + (size_t)(g + 1) * 256 + i + 8] = rtf(uu[nt][3]);
            }
        }
        return;
    }

    if (EPI == 4) {
        float* Ts   = sm;           // [128][132]
        float* psum = sm + 16896;   // [128][4]
#pragma unroll
        for (int q = 0; q < 8; q++) {
            int idx = q * 2048 + tid * 4;
            int col = idx >> 7, row = idx & 127;
            float4 v = *(const float4*)&res[(size_t)(n0 + col) * 256 + m0 + row];
            *(float4*)&Ts[col * 132 + row] = v;
        }
        __syncthreads();
#pragma unroll
        for (int mt = 0; mt < 2; mt++) {
            const int row = wm + mt * 16 + grp;
#pragma unroll
            for (int nt = 0; nt < 4; nt++) {
                const int col = wn + nt * 8 + qid * 2;
                float h00 = Ts[col * 132 + row],     h01 = Ts[(col + 1) * 132 + row];
                float h10 = Ts[col * 132 + row + 8], h11 = Ts[(col + 1) * 132 + row + 8];
                cfr[mt][nt][0] = fmaxf(cfr[mt][nt][0] * h00, MIN_POS);
                cfr[mt][nt][1] = fmaxf(cfr[mt][nt][1] * h01, MIN_POS);
                cfr[mt][nt][2] = fmaxf(cfr[mt][nt][2] * h10, MIN_POS);
                cfr[mt][nt][3] = fmaxf(cfr[mt][nt][3] * h11, MIN_POS);
            }
        }
        const int p = wid >> 2;
#pragma unroll
        for (int mt = 0; mt < 2; mt++) {
#pragma unroll
            for (int rs = 0; rs < 2; rs++) {
                float s = 0.f;
#pragma unroll
                for (int nt = 0; nt < 4; nt++) s += cfr[mt][nt][rs*2] + cfr[mt][nt][rs*2+1];
                s += __shfl_xor_sync(0xffffffffu, s, 1);
                s += __shfl_xor_sync(0xffffffffu, s, 2);
                int row = wm + mt * 16 + grp + rs * 8;
                if (qid == 0) psum[row * 4 + p] = s;
            }
        }
        __syncthreads();
        const int gc = (wid >> 3) * 2;
#pragma unroll
        for (int mt = 0; mt < 2; mt++) {
            const int rr = wm + mt * 16 + grp;
            float inv0 = 1.f / (psum[rr * 4 + gc]       + psum[rr * 4 + gc + 1]);
            float inv1 = 1.f / (psum[(rr + 8) * 4 + gc] + psum[(rr + 8) * 4 + gc + 1]);
#pragma unroll
            for (int nt = 0; nt < 4; nt++) {
                const int col = wn + nt * 8 + qid * 2;
                Ts[col * 132 + rr]           = rtf(cfr[mt][nt][0] * inv0);
                Ts[(col + 1) * 132 + rr]     = rtf(cfr[mt][nt][1] * inv0);
                Ts[col * 132 + rr + 8]       = rtf(cfr[mt][nt][2] * inv1);
                Ts[(col + 1) * 132 + rr + 8] = rtf(cfr[mt][nt][3] * inv1);
            }
        }
        __syncthreads();
#pragma unroll
        for (int q = 0; q < 8; q++) {
            int idx = q * 2048 + tid * 4;
            int col = idx >> 7, row = idx & 127;
            float4 v = *(const float4*)&Ts[col * 132 + row];
            *(float4*)&aux[(size_t)(n0 + col) * 256 + m0 + row] = v;
        }
        return;
    }

    if (EPI == 0) {
        float* psum = sm + 16896;   // [128][4]
#pragma unroll
        for (int mt = 0; mt < 2; mt++) {
#pragma unroll
            for (int nt = 0; nt < 4; nt++) {
                const int col = n0 + wn + nt * 8 + qid * 2;
                float2 bv = *(const float2*)&bias[col];
                cfr[mt][nt][0] = fmaxf(cfr[mt][nt][0] + bv.x, MIN_POS);
                cfr[mt][nt][1] = fmaxf(cfr[mt][nt][1] + bv.y, MIN_POS);
                cfr[mt][nt][2] = fmaxf(cfr[mt][nt][2] + bv.x, MIN_POS);
                cfr[mt][nt][3] = fmaxf(cfr[mt][nt][3] + bv.y, MIN_POS);
            }
        }
        const int p = wid >> 2;
#pragma unroll
        for (int mt = 0; mt < 2; mt++) {
#pragma unroll
            for (int rs = 0; rs < 2; rs++) {
                float s = 0.f;
#pragma unroll
                for (int nt = 0; nt < 4; nt++) s += cfr[mt][nt][rs*2] + cfr[mt][nt][rs*2+1];
                s += __shfl_xor_sync(0xffffffffu, s, 1);
                s += __shfl_xor_sync(0xffffffffu, s, 2);
                int row = wm + mt * 16 + grp + rs * 8;
                if (qid == 0) psum[row * 4 + p] = s;
            }
        }
        __syncthreads();
        const int gc = (wid >> 3) * 2;
#pragma unroll
        for (int mt = 0; mt < 2; mt++) {
            const int rr = wm + mt * 16 + grp;
            const size_t r0 = m0 + rr;
            float inv0 = 1.f / (psum[rr * 4 + gc]       + psum[rr * 4 + gc + 1]);
            float inv1 = 1.f / (psum[(rr + 8) * 4 + gc] + psum[(rr + 8) * 4 + gc + 1]);
#pragma unroll
            for (int nt = 0; nt < 4; nt++) {
                const int col = wn + nt * 8 + qid * 2;
                float2 o0; o0.x = cfr[mt][nt][0] * inv0; o0.y = cfr[mt][nt][1] * inv0;
                float2 o1; o1.x = cfr[mt][nt][2] * inv1; o1.y = cfr[mt][nt][3] * inv1;
                *(float2*)&C[r0 * N + n0 + col] = o0;
                *(float2*)&C[(r0 + 8) * N + n0 + col] = o1;
            }
        }
        return;
    }

#pragma unroll
    for (int mt = 0; mt < 2; mt++) {
        const size_t r0 = m0 + wm + mt * 16 + grp;
#pragma unroll
        for (int nt = 0; nt < 4; nt++) {
            const int col = n0 + wn + nt * 8 + qid * 2;
            float bx = 0.f, by = 0.f;
            if (EPI != 3) {
                float2 bv = *(const float2*)&bias[col];
                bx = bv.x; by = bv.y;
            }
            float v0 = cfr[mt][nt][0] + bx, v1 = cfr[mt][nt][1] + by;
            float v2 = cfr[mt][nt][2] + bx, v3 = cfr[mt][nt][3] + by;
            if (EPI == 1) {
                float2 ra = *(const float2*)&res[r0 * N + col];
                float2 rb = *(const float2*)&res[(r0 + 8) * N + col];
                v0 += ra.x; v1 += ra.y; v2 += rb.x; v3 += rb.y;
            } else if (EPI == 2) {
                v0 = rtf(gelu_tanh(v0)); v1 = rtf(gelu_tanh(v1));
                v2 = rtf(gelu_tanh(v2)); v3 = rtf(gelu_tanh(v3));
            }
            float2 o0; o0.x = v0; o0.y = v1;
            float2 o1; o1.x = v2; o1.y = v3;
            *(float2*)&C[r0 * N + col] = o0;
            *(float2*)&C[(r0 + 8) * N + col] = o1;
        }
    }
}

// ---------------- fused prologue: rounds + both transposes in ONE launch -----
__global__ __launch_bounds__(256) void prep_kernel(
    const float* __restrict__ ew, const float* __restrict__ ow,
    const float* __restrict__ w1, const float* __restrict__ w2,
    const float* __restrict__ gw, const float* __restrict__ h0,
    float* __restrict__ ewR, float* __restrict__ owR,
    float* __restrict__ w1R, float* __restrict__ w2R,
    float* __restrict__ gwR, float* __restrict__ gwT,
    float* __restrict__ hT)
{
    __shared__ float t[32][33];
    const int b = blockIdx.x, tid = threadIdx.x;
    if (b < 2624) {
        int i = b * 256 + tid;
        if (i >= 671744) return;
        const float* in; float* out; int off;
        if (i < 65536)        { in = ew; out = ewR; off = i; }
        else if (i < 131072)  { in = ow; out = owR; off = i - 65536; }
        else if (i < 393216)  { in = w1; out = w1R; off = i - 131072; }
        else if (i < 655360)  { in = w2; out = w2R; off = i - 393216; }
        else                  { in = gw; out = gwR; off = i - 655360; }
        float4 v = *(const float4*)&in[(size_t)off * 4];
        v.x = rtf(v.x); v.y = rtf(v.y); v.z = rtf(v.z); v.w = rtf(v.w);
        *(float4*)&out[(size_t)off * 4] = v;
        return;
    }
    const int lx = tid & 31, ly = tid >> 5;
    if (b < 2688) {
        int bb = b - 2624;
        int c0 = (bb & 7) * 32, r0 = (bb >> 3) * 32;
#pragma unroll
        for (int i = 0; i < 32; i += 8)
            t[ly + i][lx] = rtf(gw[(size_t)(r0 + ly + i) * 256 + c0 + lx]);
        __syncthreads();
#pragma unroll
        for (int i = 0; i < 32; i += 8)
            gwT[(size_t)(c0 + ly + i) * 256 + r0 + lx] = t[lx][ly + i];
        return;
    }
    {
        int bb = b - 2688;
        int bz = bb >> 7, rem = bb & 127;
        int c0 = (rem & 15) * 32, r0 = (rem >> 4) * 32;
        const float* in = h0 + (size_t)bz * 256 * 512;
        float* out = hT + (size_t)bz * 256 * 512;
#pragma unroll
        for (int i = 0; i < 32; i += 8)
            t[ly + i][lx] = rtf(in[(size_t)(r0 + ly + i) * 512 + c0 + lx]);
        __syncthreads();
#pragma unroll
        for (int i = 0; i < 32; i += 8)
            out[(size_t)(c0 + ly + i) * 256 + r0 + lx] = t[lx][ly + i];
    }
}

// ---------------- LayerNorm (tf32-rounded output) -----------------------------
__global__ __launch_bounds__(256) void ln_kernel(
    const float* __restrict__ x, const float* __restrict__ g,
    const float* __restrict__ b, float* __restrict__ out)
{
    int row  = blockIdx.x * 8 + (threadIdx.x >> 5);
    int lane = threadIdx.x & 31;
    const float* xr = x + (size_t)row * 512;
    float4 v[4];
    float s = 0.f, sq = 0.f;
#pragma unroll
    for (int w = 0; w < 4; w++) {
        v[w] = *(const float4*)&xr[w * 128 + lane * 4];
        s  += v[w].x + v[w].y + v[w].z + v[w].w;
        sq += v[w].x*v[w].x + v[w].y*v[w].y + v[w].z*v[w].z + v[w].w*v[w].w;
    }
#pragma unroll
    for (int off = 16; off > 0; off >>= 1) {
        s  += __shfl_xor_sync(0xffffffffu, s,  off);
        sq += __shfl_xor_sync(0xffffffffu, sq, off);
    }
    float mu = s * (1.f / 512.f);
    float var = sq * (1.f / 512.f) - mu * mu;
    float rstd = rsqrtf(var + 1e-5f);
    float* orow = out + (size_t)row * 512;
#pragma unroll
    for (int w = 0; w < 4; w++) {
        int c = w * 128 + lane * 4;
        float4 gv = *(const float4*)&g[c];
        float4 bv = *(const float4*)&b[c];
        float4 o;
        o.x = rtf((v[w].x - mu) * rstd * gv.x + bv.x);
        o.y = rtf((v[w].y - mu) * rstd * gv.y + bv.y);
        o.z = rtf((v[w].z - mu) * rstd * gv.z + bv.z);
        o.w = rtf((v[w].w - mu) * rstd * gv.w + bv.w);
        *(float4*)&orow[c] = o;
    }
}

// ---------------- host launcher -----------------------------------------------
extern "C" void kernel_launch(void* const* d_in, const int* in_sizes, int n_in,
                              void* d_out, int out_size)
{
    const float* x    = (const float*)d_in[0];
    const float* ew   = (const float*)d_in[1];
    const float* eb   = (const float*)d_in[2];
    const float* lw   = (const float*)d_in[3];
    const float* gw   = (const float*)d_in[4];
    const float* ow   = (const float*)d_in[5];
    const float* ob   = (const float*)d_in[6];
    const float* ln1g = (const float*)d_in[7];
    const float* ln1b = (const float*)d_in[8];
    const float* ln2g = (const float*)d_in[9];
    const float* ln2b = (const float*)d_in[10];
    const float* w1   = (const float*)d_in[11];
    const float* b1   = (const float*)d_in[12];
    const float* w2   = (const float*)d_in[13];
    const float* b2   = (const float*)d_in[14];
    const float* h0   = (const float*)d_in[15];
    float* out = (float*)d_out;

    float *xn, *xe, *hT, *u1T, *r, *xres, *mlp, *gwT, *gwR;
    float *ewR, *owR, *w1R, *w2R;
    cudaGetSymbolAddress((void**)&xn,   g_xn);
    cudaGetSymbolAddress((void**)&xe,   g_xe);
    cudaGetSymbolAddress((void**)&hT,   g_hT);
    cudaGetSymbolAddress((void**)&u1T,  g_u1T);
    cudaGetSymbolAddress((void**)&r,    g_r);
    cudaGetSymbolAddress((void**)&xres, g_xres);
    cudaGetSymbolAddress((void**)&mlp,  g_mlp);
    cudaGetSymbolAddress((void**)&gwT,  g_gwT);
    cudaGetSymbolAddress((void**)&gwR,  g_gwR);
    cudaGetSymbolAddress((void**)&ewR,  g_ewR);
    cudaGetSymbolAddress((void**)&owR,  g_owR);
    cudaGetSymbolAddress((void**)&w1R,  g_w1R);
    cudaGetSymbolAddress((void**)&w2R,  g_w2R);

    cudaFuncSetAttribute(mma_gemm<0>, cudaFuncAttributeMaxDynamicSharedMemorySize, MM_SMEM);
    cudaFuncSetAttribute(mma_gemm<1>, cudaFuncAttributeMaxDynamicSharedMemorySize, MM_SMEM);
    cudaFuncSetAttribute(mma_gemm<2>, cudaFuncAttributeMaxDynamicSharedMemorySize, MM_SMEM);
    cudaFuncSetAttribute(mma_gemm<3>, cudaFuncAttributeMaxDynamicSharedMemorySize, MM_SMEM);
    cudaFuncSetAttribute(mma_gemm<4>, cudaFuncAttributeMaxDynamicSharedMemorySize, MM_SMEM);
    cudaFuncSetAttribute(mma_gemm<5>, cudaFuncAttributeMaxDynamicSharedMemorySize, MM_SMEM);
    cudaFuncSetAttribute(mma_gemm<6>, cudaFuncAttributeMaxDynamicSharedMemorySize, MM_SMEM);

    const long long SB = 512LL * 256;
    const long long SC = 256LL * 512;

    prep_kernel<<<19072, 256>>>(ew, ow, w1, w2, gw, h0,
                                ewR, owR, w1R, w2R, gwR, gwT, hT);
    ln_kernel<<<BSROWS / 8, 256>>>(x, ln1g, ln1b, xn);
    mma_gemm<0><<<dim3(4, 256, 1), 512, MM_SMEM>>>(xn, ewR, eb, nullptr, xe, nullptr, 512, 512, 0, 0);

    for (int it = 0; it < 10; it++) {
        if (it < 9) {
            mma_gemm<5><<<dim3(4, 2, 128), 512, MM_SMEM>>>(gwT, hT, lw, xe, r, u1T, 256, 512, SB, SC);
            mma_gemm<4><<<dim3(4, 2, 128), 512, MM_SMEM>>>(gwR, u1T, nullptr, hT, hT, hT, 256, 512, SB, SC);
        } else {
            mma_gemm<6><<<dim3(4, 2, 128), 512, MM_SMEM>>>(gwT, hT, lw, xe, r, u1T, 256, 512, SB, SC);
        }
    }

    mma_gemm<1><<<dim3(4, 256, 1), 512, MM_SMEM>>>(r, owR, ob, x, xres, nullptr, 512, 512, 0, 0);
    ln_kernel<<<BSROWS / 8, 256>>>(xres, ln2g, ln2b, xn);
    mma_gemm<2><<<dim3(16, 256, 1), 512, MM_SMEM>>>(xn, w1R, b1, nullptr, mlp, nullptr, 512, 2048, 0, 0);
    mma_gemm<1><<<dim3(4, 256, 1), 512, MM_SMEM>>>(mlp, w2R, b2, xres, out, nullptr, 2048, 512, 0, 0);
}

// round 14
// speedup vs baseline: 1.5669x; 1.5669x over previous
#include <cuda_runtime.h>
#include <cuda_fp16.h>
#include <cstdint>

#define BSZ   128
#define SEQ   256
#define FDIM  512
#define EDIM  512
#define HEADS 8
#define BSROWS (BSZ*SEQ)
#define MLPD  2048
#define MIN_POS 1e-6f

// fp32 buffers (residual stream)
__device__ float g_xres[(size_t)BSROWS*FDIM];
// fp16 operand buffers
__device__ __align__(16) __half g_xn16 [(size_t)BSROWS*FDIM];
__device__ __align__(16) __half g_xe16 [(size_t)BSROWS*EDIM];
__device__ __align__(16) __half g_hT16 [(size_t)BSROWS*EDIM];   // [b,e,o]
__device__ __align__(16) __half g_u1T16[(size_t)BSROWS*EDIM];   // [b,e,i]
__device__ __align__(16) __half g_r16  [(size_t)BSROWS*EDIM];
__device__ __align__(16) __half g_mlp16[(size_t)BSROWS*MLPD];
__device__ __align__(16) __half g_gwH  [(size_t)SEQ*SEQ];
__device__ __align__(16) __half g_gwTH [(size_t)SEQ*SEQ];
__device__ __align__(16) __half g_ewH  [(size_t)EDIM*FDIM];
__device__ __align__(16) __half g_owH  [(size_t)FDIM*EDIM];
__device__ __align__(16) __half g_w1H  [(size_t)MLPD*FDIM];
__device__ __align__(16) __half g_w2H  [(size_t)FDIM*MLPD];
__device__ __align__(16) __half g_lwH  [64*64];

// ---------------- helpers -----------------------------------------------------
__device__ __forceinline__ __half hrn(float x) { return __float2half_rn(x); }
#define CP16(dst, src) \
    asm volatile("cp.async.cg.shared.global [%0], [%1], 16;" :: "r"(dst), "l"(src))
#define CP_COMMIT() asm volatile("cp.async.commit_group;" ::: "memory")
#define CP_WAIT(n)  asm volatile("cp.async.wait_group %0;" :: "n"(n) : "memory")
#define L2PF(p) asm volatile("prefetch.global.L2 [%0];" :: "l"(p))
#define LDSM4(r0, r1, r2, r3, addr) \
    asm volatile("ldmatrix.sync.aligned.m8n8.x4.shared.b16 {%0,%1,%2,%3}, [%4];" \
                 : "=r"(r0), "=r"(r1), "=r"(r2), "=r"(r3) : "r"(addr))
__device__ __forceinline__ uint32_t s2u(const void* p) {
    uint32_t a;
    asm("{ .reg .u64 t; cvta.to.shared.u64 t, %1; cvt.u32.u64 %0, t; }" : "=r"(a) : "l"(p));
    return a;
}
__device__ __forceinline__ void mma_f16(float* c, const uint32_t* a, const uint32_t* b) {
    asm volatile(
        "mma.sync.aligned.m16n8k16.row.col.f32.f16.f16.f32 "
        "{%0,%1,%2,%3}, {%4,%5,%6,%7}, {%8,%9}, {%0,%1,%2,%3};"
        : "+f"(c[0]), "+f"(c[1]), "+f"(c[2]), "+f"(c[3])
        : "r"(a[0]), "r"(a[1]), "r"(a[2]), "r"(a[3]), "r"(b[0]), "r"(b[1]));
}
static __device__ __forceinline__ float gelu_tanh(float v) {
    float t = tanhf(0.7978845608028654f * (v + 0.044715f * v * v * v));
    return 0.5f * v * (1.f + t);
}

// ---------------- fp16 mma GEMM: C[M,N]=A[M,K]@B[N,K]^T ----------------------
// 128x128 tile, 256 thr (2x4 warps, 64x32 warp tile), K-chunk 32 (fp16),
// 3-stage cp.async ring, ldmatrix b16 fragments, fp32 accum.
// EPI: 0=bias+clip+L1norm64->fp16  1=bias+res->fp32  2=bias+gelu->fp16
//      4=fused NNMF-B in-place on hT16  5=fused NNMF-A  6=NNMF-A last (r only)
#define SMPH 40                 // fp16 row stride (80 B)
#define STGB 10240              // bytes per operand per stage (128*80)
#define MM_SMEM 61440           // 3 stages x 2 operands

template <int EPI>
__global__ __launch_bounds__(256, 2) void mma_gemm(
    const __half* __restrict__ A, const __half* __restrict__ B,
    const void* __restrict__ bias, const void* __restrict__ res,
    void* __restrict__ C, __half* __restrict__ aux, int K, int N,
    long long sB, long long sC)
{
    extern __shared__ char smb[];
    const int tid = threadIdx.x, wid = tid >> 5, lane = tid & 31;
    const int grp = lane >> 2, qid = lane & 3;
    const int n0 = blockIdx.x * 128;
    const size_t m0 = (size_t)blockIdx.y * 128;
    B += (size_t)blockIdx.z * sB;
    const int wm = (wid & 1) * 64, wn = (wid >> 1) * 32;
    const uint32_t sAu = s2u(smb);

    const int t8 = lane >> 3, r8 = lane & 7;
    const int rowA = wm + (t8 & 1) * 8 + r8;
    const int segA = (t8 >> 1) * 8;            // fp16 units
    const int rowB = wn + (t8 >> 1) * 8 + r8;
    const int segB = (t8 & 1) * 8;

    auto load_chunk = [&](int st, int kt) {
        uint32_t base = sAu + (uint32_t)(st * 2 * STGB);
#pragma unroll
        for (int i = 0; i < 2; i++) {
            int id = tid + 256 * i;
            int row = id >> 2, sg = id & 3;
            CP16(base + (uint32_t)(row * 80 + sg * 16),
                 &A[(m0 + row) * K + kt + sg * 8]);
        }
        base += STGB;
#pragma unroll
        for (int i = 0; i < 2; i++) {
            int id = tid + 256 * i;
            int row = id >> 2, sg = id & 3;
            CP16(base + (uint32_t)(row * 80 + sg * 16),
                 &B[(size_t)(n0 + row) * K + kt + sg * 8]);
        }
        CP_COMMIT();
    };

    float cfr[4][4][4];
#pragma unroll
    for (int mt = 0; mt < 4; mt++)
#pragma unroll
        for (int nt = 0; nt < 4; nt++)
#pragma unroll
            for (int i = 0; i < 4; i++) cfr[mt][nt][i] = 0.f;

    const int nch = K >> 5;
    load_chunk(0, 0);
    if (nch > 1) load_chunk(1, 32);

    if (EPI == 5) {
        const __half* xh = (const __half*)res;
        int row = tid >> 1, l = tid & 1;
        L2PF(&xh[(m0 + row) * (size_t)N + n0 + l * 64]);
        if (tid < 64) L2PF(&((const __half*)bias)[tid * 64]);
    } else if (EPI == 4) {
        const __half* hh = (const __half*)res;
        int col = tid >> 1, l = tid & 1;
        L2PF(&hh[((size_t)blockIdx.z * sC) + (size_t)(n0 + col) * 256 + m0 + l * 64]);
    }

    for (int c = 0; c < nch; c++) {
        if (c + 1 < nch) CP_WAIT(1);
        else             CP_WAIT(0);
        __syncthreads();
        if (c + 2 < nch) load_chunk((c + 2) % 3, (c + 2) * 32);
        const uint32_t sAs = sAu + (uint32_t)((c % 3) * 2 * STGB);
        const uint32_t sBs = sAs + STGB;
#pragma unroll
        for (int kk = 0; kk < 32; kk += 16) {
            uint32_t af[4][4], bf[2][4];
#pragma unroll
            for (int mt = 0; mt < 4; mt++)
                LDSM4(af[mt][0], af[mt][1], af[mt][2], af[mt][3],
                      sAs + (uint32_t)((rowA + mt * 16) * SMPH + kk + segA) * 2);
#pragma unroll
            for (int ntp = 0; ntp < 2; ntp++)
                LDSM4(bf[ntp][0], bf[ntp][1], bf[ntp][2], bf[ntp][3],
                      sBs + (uint32_t)((rowB + ntp * 16) * SMPH + kk + segB) * 2);
#pragma unroll
            for (int mt = 0; mt < 4; mt++)
#pragma unroll
                for (int nt = 0; nt < 4; nt++)
                    mma_f16(cfr[mt][nt], af[mt], &bf[nt >> 1][(nt & 1) * 2]);
        }
    }
    __syncthreads();

    if (EPI == 5 || EPI == 6) {
        __half* t1s = (__half*)smb;              // [128][136]
        __half* lwT = (__half*)(smb + 34816);    // [64][72] lwT[f][g]
        __half* lwS = (__half*)(smb + 44032);    // [64][72] lwS[g][f]
        const uint32_t sT = sAu, sL1 = sAu + 34816, sL2 = sAu + 44032;
        const __half* lwh = (const __half*)bias;
        const __half* xeh = (const __half*)res + (size_t)blockIdx.z * sC;
        __half* rh = (__half*)C + (size_t)blockIdx.z * sC;
        __half* u1h = aux + (size_t)blockIdx.z * sC;
#pragma unroll
        for (int q = 0; q < 16; q++) {
            int idx = q * 256 + tid;
            int g = idx >> 6, f = idx & 63;
            __half v = lwh[idx];
            lwT[f * 72 + g] = v;
            lwS[g * 72 + f] = v;
        }
#pragma unroll
        for (int mt = 0; mt < 4; mt++) {
            const int row = wm + mt * 16 + grp;
#pragma unroll
            for (int nt = 0; nt < 4; nt++) {
                const int col = wn + nt * 8 + qid * 2;
                t1s[row * 136 + col]           = hrn(cfr[mt][nt][0]);
                t1s[row * 136 + col + 1]       = hrn(cfr[mt][nt][1]);
                t1s[(row + 8) * 136 + col]     = hrn(cfr[mt][nt][2]);
                t1s[(row + 8) * 136 + col + 1] = hrn(cfr[mt][nt][3]);
            }
        }
        __syncthreads();

        const int wm16 = wid * 16;
        const uint32_t aB0 = sT + (uint32_t)((wm16 + (t8 & 1) * 8 + r8) * 136 + (t8 >> 1) * 8) * 2;
        const int bRow2 = (t8 >> 1) * 8 + r8;
        const uint32_t bOff = (uint32_t)((t8 & 1) * 8) * 2;

#pragma unroll
        for (int hp = 0; hp < 2; hp++) {
            const uint32_t aB = aB0 + (uint32_t)(hp * 64) * 2;
            float rc[8][4];
#pragma unroll
            for (int nt = 0; nt < 8; nt++)
#pragma unroll
                for (int j = 0; j < 4; j++) rc[nt][j] = 0.f;
#pragma unroll
            for (int kk = 0; kk < 64; kk += 16) {
                uint32_t af[4], bf[4][4];
                LDSM4(af[0], af[1], af[2], af[3], aB + (uint32_t)kk * 2);
#pragma unroll
                for (int n2 = 0; n2 < 4; n2++)
                    LDSM4(bf[n2][0], bf[n2][1], bf[n2][2], bf[n2][3],
                          sL1 + (uint32_t)((n2 * 16 + bRow2) * 72 + kk) * 2 + bOff);
#pragma unroll
                for (int nt = 0; nt < 8; nt++)
                    mma_f16(rc[nt], af, &bf[nt >> 1][(nt & 1) * 2]);
            }
            float s0 = 0.f, s1 = 0.f;
#pragma unroll
            for (int nt = 0; nt < 8; nt++) {
#pragma unroll
                for (int j = 0; j < 4; j++) rc[nt][j] = fmaxf(rc[nt][j], MIN_POS);
                s0 += rc[nt][0] + rc[nt][1];
                s1 += rc[nt][2] + rc[nt][3];
            }
            s0 += __shfl_xor_sync(0xffffffffu, s0, 1);
            s0 += __shfl_xor_sync(0xffffffffu, s0, 2);
            s1 += __shfl_xor_sync(0xffffffffu, s1, 1);
            s1 += __shfl_xor_sync(0xffffffffu, s1, 2);

            const size_t ra = (m0 + wm16 + grp) * (size_t)N + n0 + hp * 64;
            const size_t rb = ra + 8 * (size_t)N;

            if (EPI == 6) {
                const float inv0 = 1.f / s0, inv1 = 1.f / s1;
#pragma unroll
                for (int nt = 0; nt < 8; nt++) {
                    const int f = nt * 8 + qid * 2;
                    *(__half2*)&rh[ra + f] = __floats2half2_rn(rc[nt][0] * inv0, rc[nt][1] * inv0);
                    *(__half2*)&rh[rb + f] = __floats2half2_rn(rc[nt][2] * inv1, rc[nt][3] * inv1);
                }
                continue;
            }

            // xr = xe*s/rc -> t1s (warp-private rows)
#pragma unroll
            for (int nt = 0; nt < 8; nt++) {
                const int f = nt * 8 + qid * 2;
                float2 x0 = __half22float2(*(const __half2*)&xeh[ra + f]);
                float2 x1 = __half22float2(*(const __half2*)&xeh[rb + f]);
                t1s[(wm16 + grp) * 136 + hp * 64 + f]         = hrn(x0.x * s0 / rc[nt][0]);
                t1s[(wm16 + grp) * 136 + hp * 64 + f + 1]     = hrn(x0.y * s0 / rc[nt][1]);
                t1s[(wm16 + grp + 8) * 136 + hp * 64 + f]     = hrn(x1.x * s1 / rc[nt][2]);
                t1s[(wm16 + grp + 8) * 136 + hp * 64 + f + 1] = hrn(x1.y * s1 / rc[nt][3]);
            }
            __syncwarp();

            float uu[8][4];
#pragma unroll
            for (int nt = 0; nt < 8; nt++)
#pragma unroll
                for (int j = 0; j < 4; j++) uu[nt][j] = 0.f;
#pragma unroll
            for (int kk = 0; kk < 64; kk += 16) {
                uint32_t af[4], bf[4][4];
                LDSM4(af[0], af[1], af[2], af[3], aB + (uint32_t)kk * 2);
#pragma unroll
                for (int n2 = 0; n2 < 4; n2++)
                    LDSM4(bf[n2][0], bf[n2][1], bf[n2][2], bf[n2][3],
                          sL2 + (uint32_t)((n2 * 16 + bRow2) * 72 + kk) * 2 + bOff);
#pragma unroll
                for (int nt = 0; nt < 8; nt++)
                    mma_f16(uu[nt], af, &bf[nt >> 1][(nt & 1) * 2]);
            }
            {
                const size_t eb = (size_t)(n0 + hp * 64) * 256 + m0;
                const int i = wm16 + grp;
#pragma unroll
                for (int nt = 0; nt < 8; nt++) {
                    const int g = nt * 8 + qid * 2;
                    u1h[eb + (size_t)g * 256 + i]           = hrn(uu[nt][0]);
                    u1h[eb + (size_t)(g + 1) * 256 + i]     = hrn(uu[nt][1]);
                    u1h[eb + (size_t)g * 256 + i + 8]       = hrn(uu[nt][2]);
                    u1h[eb + (size_t)(g + 1) * 256 + i + 8] = hrn(uu[nt][3]);
                }
            }
        }
        return;
    }

    if (EPI == 4) {
        __half* Ts  = (__half*)smb;              // [128][136]
        float* psum = (float*)(smb + 34816);     // [128][5]
        const __half* hIn = (const __half*)res + (size_t)blockIdx.z * sC;
        __half* hOut = aux + (size_t)blockIdx.z * sC;
#pragma unroll
        for (int q = 0; q < 8; q++) {
            int idx = q * 2048 + tid * 8;
            int col = idx >> 7, row = idx & 127;
            *(uint4*)&Ts[col * 136 + row] =
                *(const uint4*)&hIn[(size_t)(n0 + col) * 256 + m0 + row];
        }
        __syncthreads();
#pragma unroll
        for (int mt = 0; mt < 4; mt++) {
            const int row = wm + mt * 16 + grp;
#pragma unroll
            for (int nt = 0; nt < 4; nt++) {
                const int col = wn + nt * 8 + qid * 2;
                float h00 = __half2float(Ts[col * 136 + row]);
                float h01 = __half2float(Ts[(col + 1) * 136 + row]);
                float h10 = __half2float(Ts[col * 136 + row + 8]);
                float h11 = __half2float(Ts[(col + 1) * 136 + row + 8]);
                cfr[mt][nt][0] = fmaxf(cfr[mt][nt][0] * h00, MIN_POS);
                cfr[mt][nt][1] = fmaxf(cfr[mt][nt][1] * h01, MIN_POS);
                cfr[mt][nt][2] = fmaxf(cfr[mt][nt][2] * h10, MIN_POS);
                cfr[mt][nt][3] = fmaxf(cfr[mt][nt][3] * h11, MIN_POS);
            }
        }
#pragma unroll
        for (int mt = 0; mt < 4; mt++) {
#pragma unroll
            for (int rs = 0; rs < 2; rs++) {
                float s = 0.f;
#pragma unroll
                for (int nt = 0; nt < 4; nt++) s += cfr[mt][nt][rs*2] + cfr[mt][nt][rs*2+1];
                s += __shfl_xor_sync(0xffffffffu, s, 1);
                s += __shfl_xor_sync(0xffffffffu, s, 2);
                int row = wm + mt * 16 + grp + rs * 8;
                if (qid == 0) psum[row * 5 + (wid >> 1)] = s;
            }
        }
        __syncthreads();
        const int gc = (wid >> 2) * 2;
#pragma unroll
        for (int mt = 0; mt < 4; mt++) {
            const int rr = wm + mt * 16 + grp;
            float inv0 = 1.f / (psum[rr * 5 + gc]       + psum[rr * 5 + gc + 1]);
            float inv1 = 1.f / (psum[(rr + 8) * 5 + gc] + psum[(rr + 8) * 5 + gc + 1]);
#pragma unroll
            for (int nt = 0; nt < 4; nt++) {
                const int col = wn + nt * 8 + qid * 2;
                Ts[col * 136 + rr]           = hrn(cfr[mt][nt][0] * inv0);
                Ts[(col + 1) * 136 + rr]     = hrn(cfr[mt][nt][1] * inv0);
                Ts[col * 136 + rr + 8]       = hrn(cfr[mt][nt][2] * inv1);
                Ts[(col + 1) * 136 + rr + 8] = hrn(cfr[mt][nt][3] * inv1);
            }
        }
        __syncthreads();
#pragma unroll
        for (int q = 0; q < 8; q++) {
            int idx = q * 2048 + tid * 8;
            int col = idx >> 7, row = idx & 127;
            *(uint4*)&hOut[(size_t)(n0 + col) * 256 + m0 + row] =
                *(const uint4*)&Ts[col * 136 + row];
        }
        return;
    }

    if (EPI == 0) {
        float* psum = (float*)(smb + 34816);     // [128][5]
        const float* biasF = (const float*)bias;
        __half* Ch = (__half*)C;
#pragma unroll
        for (int mt = 0; mt < 4; mt++) {
#pragma unroll
            for (int nt = 0; nt < 4; nt++) {
                const int col = n0 + wn + nt * 8 + qid * 2;
                float2 bv = *(const float2*)&biasF[col];
                cfr[mt][nt][0] = fmaxf(cfr[mt][nt][0] + bv.x, MIN_POS);
                cfr[mt][nt][1] = fmaxf(cfr[mt][nt][1] + bv.y, MIN_POS);
                cfr[mt][nt][2] = fmaxf(cfr[mt][nt][2] + bv.x, MIN_POS);
                cfr[mt][nt][3] = fmaxf(cfr[mt][nt][3] + bv.y, MIN_POS);
            }
        }
#pragma unroll
        for (int mt = 0; mt < 4; mt++) {
#pragma unroll
            for (int rs = 0; rs < 2; rs++) {
                float s = 0.f;
#pragma unroll
                for (int nt = 0; nt < 4; nt++) s += cfr[mt][nt][rs*2] + cfr[mt][nt][rs*2+1];
                s += __shfl_xor_sync(0xffffffffu, s, 1);
                s += __shfl_xor_sync(0xffffffffu, s, 2);
                int row = wm + mt * 16 + grp + rs * 8;
                if (qid == 0) psum[row * 5 + (wid >> 1)] = s;
            }
        }
        __syncthreads();
        const int gc = (wid >> 2) * 2;
#pragma unroll
        for (int mt = 0; mt < 4; mt++) {
            const int rr = wm + mt * 16 + grp;
            const size_t r0 = m0 + rr;
            float inv0 = 1.f / (psum[rr * 5 + gc]       + psum[rr * 5 + gc + 1]);
            float inv1 = 1.f / (psum[(rr + 8) * 5 + gc] + psum[(rr + 8) * 5 + gc + 1]);
#pragma unroll
            for (int nt = 0; nt < 4; nt++) {
                const int col = wn + nt * 8 + qid * 2;
                *(__half2*)&Ch[r0 * N + n0 + col] =
                    __floats2half2_rn(cfr[mt][nt][0] * inv0, cfr[mt][nt][1] * inv0);
                *(__half2*)&Ch[(r0 + 8) * N + n0 + col] =
                    __floats2half2_rn(cfr[mt][nt][2] * inv1, cfr[mt][nt][3] * inv1);
            }
        }
        return;
    }

    // EPI 1 (fp32 out + residual) and EPI 2 (gelu -> fp16)
    const float* biasF = (const float*)bias;
#pragma unroll
    for (int mt = 0; mt < 4; mt++) {
        const size_t r0 = m0 + wm + mt * 16 + grp;
#pragma unroll
        for (int nt = 0; nt < 4; nt++) {
            const int col = n0 + wn + nt * 8 + qid * 2;
            float2 bv = *(const float2*)&biasF[col];
            float v0 = cfr[mt][nt][0] + bv.x, v1 = cfr[mt][nt][1] + bv.y;
            float v2 = cfr[mt][nt][2] + bv.x, v3 = cfr[mt][nt][3] + bv.y;
            if (EPI == 1) {
                const float* resF = (const float*)res;
                float* Cf = (float*)C;
                float2 ra = *(const float2*)&resF[r0 * N + col];
                float2 rb = *(const float2*)&resF[(r0 + 8) * N + col];
                float2 o0; o0.x = v0 + ra.x; o0.y = v1 + ra.y;
                float2 o1; o1.x = v2 + rb.x; o1.y = v3 + rb.y;
                *(float2*)&Cf[r0 * N + col] = o0;
                *(float2*)&Cf[(r0 + 8) * N + col] = o1;
            } else {  // EPI == 2
                __half* Ch = (__half*)C;
                *(__half2*)&Ch[r0 * N + col] =
                    __floats2half2_rn(gelu_tanh(v0), gelu_tanh(v1));
                *(__half2*)&Ch[(r0 + 8) * N + col] =
                    __floats2half2_rn(gelu_tanh(v2), gelu_tanh(v3));
            }
        }
    }
}

// ---------------- fused prologue: fp16 rounds + both transposes --------------
// blocks [0,2628): convert 6 weight tensors (672768 float4)
// [2628,2692): gw->gwT ; [2692,19076): h0->hT16
__global__ __launch_bounds__(256) void prep_kernel(
    const float* __restrict__ ew, const float* __restrict__ ow,
    const float* __restrict__ w1, const float* __restrict__ w2,
    const float* __restrict__ gw, const float* __restrict__ lw,
    const float* __restrict__ h0,
    __half* __restrict__ ewH, __half* __restrict__ owH,
    __half* __restrict__ w1H, __half* __restrict__ w2H,
    __half* __restrict__ gwH, __half* __restrict__ lwH,
    __half* __restrict__ gwTH, __half* __restrict__ hT16)
{
    __shared__ float t[32][33];
    const int b = blockIdx.x, tid = threadIdx.x;
    if (b < 2628) {
        int i = b * 256 + tid;
        if (i >= 672768) return;
        const float* in; __half* out; int off;
        if (i < 65536)        { in = ew; out = ewH; off = i; }
        else if (i < 131072)  { in = ow; out = owH; off = i - 65536; }
        else if (i < 393216)  { in = w1; out = w1H; off = i - 131072; }
        else if (i < 655360)  { in = w2; out = w2H; off = i - 393216; }
        else if (i < 671744)  { in = gw; out = gwH; off = i - 655360; }
        else                  { in = lw; out = lwH; off = i - 671744; }
        float4 v = *(const float4*)&in[(size_t)off * 4];
        *(__half2*)&out[(size_t)off * 4]     = __floats2half2_rn(v.x, v.y);
        *(__half2*)&out[(size_t)off * 4 + 2] = __floats2half2_rn(v.z, v.w);
        return;
    }
    const int lx = tid & 31, ly = tid >> 5;
    if (b < 2692) {
        int bb = b - 2628;
        int c0 = (bb & 7) * 32, r0 = (bb >> 3) * 32;
#pragma unroll
        for (int i = 0; i < 32; i += 8)
            t[ly + i][lx] = gw[(size_t)(r0 + ly + i) * 256 + c0 + lx];
        __syncthreads();
#pragma unroll
        for (int i = 0; i < 32; i += 8)
            gwTH[(size_t)(c0 + ly + i) * 256 + r0 + lx] = hrn(t[lx][ly + i]);
        return;
    }
    {
        int bb = b - 2692;
        int bz = bb >> 7, rem = bb & 127;
        int c0 = (rem & 15) * 32, r0 = (rem >> 4) * 32;
        const float* in = h0 + (size_t)bz * 256 * 512;
        __half* out = hT16 + (size_t)bz * 256 * 512;
#pragma unroll
        for (int i = 0; i < 32; i += 8)
            t[ly + i][lx] = in[(size_t)(r0 + ly + i) * 512 + c0 + lx];
        __syncthreads();
#pragma unroll
        for (int i = 0; i < 32; i += 8)
            out[(size_t)(c0 + ly + i) * 256 + r0 + lx] = hrn(t[lx][ly + i]);
    }
}

// ---------------- LayerNorm (fp32 in -> fp16 out) ----------------------------
__global__ __launch_bounds__(256) void ln_kernel(
    const float* __restrict__ x, const float* __restrict__ g,
    const float* __restrict__ b, __half* __restrict__ out)
{
    int row  = blockIdx.x * 8 + (threadIdx.x >> 5);
    int lane = threadIdx.x & 31;
    const float* xr = x + (size_t)row * 512;
    float4 v[4];
    float s = 0.f, sq = 0.f;
#pragma unroll
    for (int w = 0; w < 4; w++) {
        v[w] = *(const float4*)&xr[w * 128 + lane * 4];
        s  += v[w].x + v[w].y + v[w].z + v[w].w;
        sq += v[w].x*v[w].x + v[w].y*v[w].y + v[w].z*v[w].z + v[w].w*v[w].w;
    }
#pragma unroll
    for (int off = 16; off > 0; off >>= 1) {
        s  += __shfl_xor_sync(0xffffffffu, s,  off);
        sq += __shfl_xor_sync(0xffffffffu, sq, off);
    }
    float mu = s * (1.f / 512.f);
    float var = sq * (1.f / 512.f) - mu * mu;
    float rstd = rsqrtf(var + 1e-5f);
    __half* orow = out + (size_t)row * 512;
#pragma unroll
    for (int w = 0; w < 4; w++) {
        int c = w * 128 + lane * 4;
        float4 gv = *(const float4*)&g[c];
        float4 bv = *(const float4*)&b[c];
        *(__half2*)&orow[c] = __floats2half2_rn(
            (v[w].x - mu) * rstd * gv.x + bv.x, (v[w].y - mu) * rstd * gv.y + bv.y);
        *(__half2*)&orow[c + 2] = __floats2half2_rn(
            (v[w].z - mu) * rstd * gv.z + bv.z, (v[w].w - mu) * rstd * gv.w + bv.w);
    }
}

// ---------------- host launcher -----------------------------------------------
extern "C" void kernel_launch(void* const* d_in, const int* in_sizes, int n_in,
                              void* d_out, int out_size)
{
    const float* x    = (const float*)d_in[0];
    const float* ew   = (const float*)d_in[1];
    const float* eb   = (const float*)d_in[2];
    const float* lw   = (const float*)d_in[3];
    const float* gw   = (const float*)d_in[4];
    const float* ow   = (const float*)d_in[5];
    const float* ob   = (const float*)d_in[6];
    const float* ln1g = (const float*)d_in[7];
    const float* ln1b = (const float*)d_in[8];
    const float* ln2g = (const float*)d_in[9];
    const float* ln2b = (const float*)d_in[10];
    const float* w1   = (const float*)d_in[11];
    const float* b1   = (const float*)d_in[12];
    const float* w2   = (const float*)d_in[13];
    const float* b2   = (const float*)d_in[14];
    const float* h0   = (const float*)d_in[15];
    float* out = (float*)d_out;

    float* xres;
    __half *xn, *xe, *hT, *u1T, *r, *mlp, *gwH, *gwTH, *ewH, *owH, *w1H, *w2H, *lwH;
    cudaGetSymbolAddress((void**)&xres, g_xres);
    cudaGetSymbolAddress((void**)&xn,   g_xn16);
    cudaGetSymbolAddress((void**)&xe,   g_xe16);
    cudaGetSymbolAddress((void**)&hT,   g_hT16);
    cudaGetSymbolAddress((void**)&u1T,  g_u1T16);
    cudaGetSymbolAddress((void**)&r,    g_r16);
    cudaGetSymbolAddress((void**)&mlp,  g_mlp16);
    cudaGetSymbolAddress((void**)&gwH,  g_gwH);
    cudaGetSymbolAddress((void**)&gwTH, g_gwTH);
    cudaGetSymbolAddress((void**)&ewH,  g_ewH);
    cudaGetSymbolAddress((void**)&owH,  g_owH);
    cudaGetSymbolAddress((void**)&w1H,  g_w1H);
    cudaGetSymbolAddress((void**)&w2H,  g_w2H);
    cudaGetSymbolAddress((void**)&lwH,  g_lwH);

    cudaFuncSetAttribute(mma_gemm<0>, cudaFuncAttributeMaxDynamicSharedMemorySize, MM_SMEM);
    cudaFuncSetAttribute(mma_gemm<1>, cudaFuncAttributeMaxDynamicSharedMemorySize, MM_SMEM);
    cudaFuncSetAttribute(mma_gemm<2>, cudaFuncAttributeMaxDynamicSharedMemorySize, MM_SMEM);
    cudaFuncSetAttribute(mma_gemm<4>, cudaFuncAttributeMaxDynamicSharedMemorySize, MM_SMEM);
    cudaFuncSetAttribute(mma_gemm<5>, cudaFuncAttributeMaxDynamicSharedMemorySize, MM_SMEM);
    cudaFuncSetAttribute(mma_gemm<6>, cudaFuncAttributeMaxDynamicSharedMemorySize, MM_SMEM);

    const long long SB = 512LL * 256;
    const long long SC = 256LL * 512;

    prep_kernel<<<19076, 256>>>(ew, ow, w1, w2, gw, lw, h0,
                                ewH, owH, w1H, w2H, gwH, lwH, gwTH, hT);
    ln_kernel<<<BSROWS / 8, 256>>>(x, ln1g, ln1b, xn);
    mma_gemm<0><<<dim3(4, 256, 1), 256, MM_SMEM>>>(xn, ewH, eb, nullptr, xe, nullptr, 512, 512, 0, 0);

    for (int it = 0; it < 10; it++) {
        if (it < 9) {
            mma_gemm<5><<<dim3(4, 2, 128), 256, MM_SMEM>>>(gwTH, hT, lwH, xe, r, u1T, 256, 512, SB, SC);
            mma_gemm<4><<<dim3(4, 2, 128), 256, MM_SMEM>>>(gwH, u1T, nullptr, hT, hT, hT, 256, 512, SB, SC);
        } else {
            mma_gemm<6><<<dim3(4, 2, 128), 256, MM_SMEM>>>(gwTH, hT, lwH, xe, r, u1T, 256, 512, SB, SC);
        }
    }

    mma_gemm<1><<<dim3(4, 256, 1), 256, MM_SMEM>>>(r, owH, ob, x, xres, nullptr, 512, 512, 0, 0);
    ln_kernel<<<BSROWS / 8, 256>>>(xres, ln2g, ln2b, xn);
    mma_gemm<2><<<dim3(16, 256, 1), 256, MM_SMEM>>>(xn, w1H, b1, nullptr, mlp, nullptr, 512, 2048, 0, 0);
    mma_gemm<1><<<dim3(4, 256, 1), 256, MM_SMEM>>>(mlp, w2H, b2, xres, out, nullptr, 2048, 512, 0, 0);
}

// round 15
// speedup vs baseline: 1.6444x; 1.0494x over previous
#include <cuda_runtime.h>
#include <cuda_fp16.h>
#include <cstdint>

#define BSZ   128
#define SEQ   256
#define FDIM  512
#define EDIM  512
#define HEADS 8
#define BSROWS (BSZ*SEQ)
#define MLPD  2048
#define MIN_POS 1e-6f

__device__ float g_xres[(size_t)BSROWS*FDIM];
__device__ __align__(16) __half g_xn16 [(size_t)BSROWS*FDIM];
__device__ __align__(16) __half g_xe16 [(size_t)BSROWS*EDIM];
__device__ __align__(16) __half g_hT16 [(size_t)BSROWS*EDIM];
__device__ __align__(16) __half g_u1T16[(size_t)BSROWS*EDIM];
__device__ __align__(16) __half g_r16  [(size_t)BSROWS*EDIM];
__device__ __align__(16) __half g_mlp16[(size_t)BSROWS*MLPD];
__device__ __align__(16) __half g_gwH  [(size_t)SEQ*SEQ];
__device__ __align__(16) __half g_gwTH [(size_t)SEQ*SEQ];
__device__ __align__(16) __half g_ewH  [(size_t)EDIM*FDIM];
__device__ __align__(16) __half g_owH  [(size_t)FDIM*EDIM];
__device__ __align__(16) __half g_w1H  [(size_t)MLPD*FDIM];
__device__ __align__(16) __half g_w2H  [(size_t)FDIM*MLPD];
__device__ __align__(16) __half g_lwH  [64*64];

// ---------------- helpers -----------------------------------------------------
__device__ __forceinline__ __half hrn(float x) { return __float2half_rn(x); }
#define CP16(dst, src) \
    asm volatile("cp.async.cg.shared.global [%0], [%1], 16;" :: "r"(dst), "l"(src))
#define CP_COMMIT() asm volatile("cp.async.commit_group;" ::: "memory")
#define CP_WAIT(n)  asm volatile("cp.async.wait_group %0;" :: "n"(n) : "memory")
#define L2PF(p) asm volatile("prefetch.global.L2 [%0];" :: "l"(p))
#define LDSM4(r0, r1, r2, r3, addr) \
    asm volatile("ldmatrix.sync.aligned.m8n8.x4.shared.b16 {%0,%1,%2,%3}, [%4];" \
                 : "=r"(r0), "=r"(r1), "=r"(r2), "=r"(r3) : "r"(addr))
__device__ __forceinline__ uint32_t s2u(const void* p) {
    uint32_t a;
    asm("{ .reg .u64 t; cvta.to.shared.u64 t, %1; cvt.u32.u64 %0, t; }" : "=r"(a) : "l"(p));
    return a;
}
__device__ __forceinline__ void mma_f16(float* c, const uint32_t* a, const uint32_t* b) {
    asm volatile(
        "mma.sync.aligned.m16n8k16.row.col.f32.f16.f16.f32 "
        "{%0,%1,%2,%3}, {%4,%5,%6,%7}, {%8,%9}, {%0,%1,%2,%3};"
        : "+f"(c[0]), "+f"(c[1]), "+f"(c[2]), "+f"(c[3])
        : "r"(a[0]), "r"(a[1]), "r"(a[2]), "r"(a[3]), "r"(b[0]), "r"(b[1]));
}
static __device__ __forceinline__ float gelu_tanh(float v) {
    float t = tanhf(0.7978845608028654f * (v + 0.044715f * v * v * v));
    return 0.5f * v * (1.f + t);
}

// ---------------- fp16 mma GEMM: C[M,N]=A[M,K]@B[N,K]^T ----------------------
// 128x128 tile, 512 threads (4x4 warps, 32x32 warp tile), K-chunk 32 fp16,
// 3-stage cp.async ring, ldmatrix b16, fp32 accum.
// EPI: 0=bias+clip+L1norm64->fp16  1=bias+res->fp32  2=bias+gelu->fp16
//      4=fused NNMF-B in-place on hT16  5=fused NNMF-A  6=NNMF-A last (r only)
#define SMPH 40
#define STGB 10240
#define MM_SMEM 61440

template <int EPI>
__global__ __launch_bounds__(512, 2) void mma_gemm(
    const __half* __restrict__ A, const __half* __restrict__ B,
    const void* __restrict__ bias, const void* __restrict__ res,
    void* __restrict__ C, __half* __restrict__ aux, int K, int N,
    long long sB, long long sC)
{
    extern __shared__ char smb[];
    const int tid = threadIdx.x, wid = tid >> 5, lane = tid & 31;
    const int grp = lane >> 2, qid = lane & 3;
    const int n0 = blockIdx.x * 128;
    const size_t m0 = (size_t)blockIdx.y * 128;
    B += (size_t)blockIdx.z * sB;
    const int wm = (wid & 3) * 32, wn = (wid >> 2) * 32;
    const uint32_t sAu = s2u(smb);

    const int t8 = lane >> 3, r8 = lane & 7;
    const int rowA = wm + (t8 & 1) * 8 + r8;
    const int segA = (t8 >> 1) * 8;
    const int rowB = wn + (t8 >> 1) * 8 + r8;
    const int segB = (t8 & 1) * 8;

    auto load_chunk = [&](int st, int kt) {
        uint32_t base = sAu + (uint32_t)(st * 2 * STGB);
        {
            int row = tid >> 2, sg = tid & 3;
            CP16(base + (uint32_t)(row * 80 + sg * 16),
                 &A[(m0 + row) * K + kt + sg * 8]);
            CP16(base + STGB + (uint32_t)(row * 80 + sg * 16),
                 &B[(size_t)(n0 + row) * K + kt + sg * 8]);
        }
        CP_COMMIT();
    };

    float cfr[2][4][4];
#pragma unroll
    for (int mt = 0; mt < 2; mt++)
#pragma unroll
        for (int nt = 0; nt < 4; nt++)
#pragma unroll
            for (int i = 0; i < 4; i++) cfr[mt][nt][i] = 0.f;

    const int nch = K >> 5;
    load_chunk(0, 0);
    if (nch > 1) load_chunk(1, 32);

    if (EPI == 5) {
        const __half* xh = (const __half*)res;
        if (tid < 256) {
            int row = tid >> 1, l = tid & 1;
            L2PF(&xh[(m0 + row) * (size_t)N + n0 + l * 64]);
        }
        if (tid < 64) L2PF(&((const __half*)bias)[tid * 64]);
    } else if (EPI == 4) {
        const __half* hh = (const __half*)res;
        if (tid < 256) {
            int col = tid >> 1, l = tid & 1;
            L2PF(&hh[((size_t)blockIdx.z * sC) + (size_t)(n0 + col) * 256 + m0 + l * 64]);
        }
    }

    for (int c = 0; c < nch; c++) {
        if (c + 1 < nch) CP_WAIT(1);
        else             CP_WAIT(0);
        __syncthreads();
        if (c + 2 < nch) load_chunk((c + 2) % 3, (c + 2) * 32);
        const uint32_t sAs = sAu + (uint32_t)((c % 3) * 2 * STGB);
        const uint32_t sBs = sAs + STGB;
#pragma unroll
        for (int kk = 0; kk < 32; kk += 16) {
            uint32_t af[2][4], bf[2][4];
#pragma unroll
            for (int mt = 0; mt < 2; mt++)
                LDSM4(af[mt][0], af[mt][1], af[mt][2], af[mt][3],
                      sAs + (uint32_t)((rowA + mt * 16) * SMPH + kk + segA) * 2);
#pragma unroll
            for (int ntp = 0; ntp < 2; ntp++)
                LDSM4(bf[ntp][0], bf[ntp][1], bf[ntp][2], bf[ntp][3],
                      sBs + (uint32_t)((rowB + ntp * 16) * SMPH + kk + segB) * 2);
#pragma unroll
            for (int mt = 0; mt < 2; mt++)
#pragma unroll
                for (int nt = 0; nt < 4; nt++)
                    mma_f16(cfr[mt][nt], af[mt], &bf[nt >> 1][(nt & 1) * 2]);
        }
    }
    __syncthreads();

    if (EPI == 5 || EPI == 6) {
        __half* t1s = (__half*)smb;              // [128][136]
        __half* lwT = (__half*)(smb + 34816);    // [64][72]
        __half* lwS = (__half*)(smb + 44032);    // [64][72]
        const uint32_t sT = sAu, sL1 = sAu + 34816, sL2 = sAu + 44032;
        const __half* lwh = (const __half*)bias;
        const __half* xeh = (const __half*)res + (size_t)blockIdx.z * sC;
        __half* rh = (__half*)C + (size_t)blockIdx.z * sC;
        __half* u1h = aux + (size_t)blockIdx.z * sC;
#pragma unroll
        for (int q = 0; q < 8; q++) {
            int idx = q * 512 + tid;
            int g = idx >> 6, f = idx & 63;
            __half v = lwh[idx];
            lwT[f * 72 + g] = v;
            lwS[g * 72 + f] = v;
        }
#pragma unroll
        for (int mt = 0; mt < 2; mt++) {
            const int row = wm + mt * 16 + grp;
#pragma unroll
            for (int nt = 0; nt < 4; nt++) {
                const int col = wn + nt * 8 + qid * 2;
                t1s[row * 136 + col]           = hrn(cfr[mt][nt][0]);
                t1s[row * 136 + col + 1]       = hrn(cfr[mt][nt][1]);
                t1s[(row + 8) * 136 + col]     = hrn(cfr[mt][nt][2]);
                t1s[(row + 8) * 136 + col + 1] = hrn(cfr[mt][nt][3]);
            }
        }
        __syncthreads();

        // warps 0-7: hp=0 (cols 0-63); warps 8-15: hp=1 (cols 64-127)
        const int hp = wid >> 3, wm16 = (wid & 7) * 16;
        const uint32_t aB = sT + (uint32_t)((wm16 + (t8 & 1) * 8 + r8) * 136 + (t8 >> 1) * 8 + hp * 64) * 2;
        const int bRow2 = (t8 >> 1) * 8 + r8;
        const uint32_t bOff = (uint32_t)((t8 & 1) * 8) * 2;

        float rc[8][4];
#pragma unroll
        for (int nt = 0; nt < 8; nt++)
#pragma unroll
            for (int j = 0; j < 4; j++) rc[nt][j] = 0.f;
#pragma unroll
        for (int kk = 0; kk < 64; kk += 16) {
            uint32_t af[4], bf[4][4];
            LDSM4(af[0], af[1], af[2], af[3], aB + (uint32_t)kk * 2);
#pragma unroll
            for (int n2 = 0; n2 < 4; n2++)
                LDSM4(bf[n2][0], bf[n2][1], bf[n2][2], bf[n2][3],
                      sL1 + (uint32_t)((n2 * 16 + bRow2) * 72 + kk) * 2 + bOff);
#pragma unroll
            for (int nt = 0; nt < 8; nt++)
                mma_f16(rc[nt], af, &bf[nt >> 1][(nt & 1) * 2]);
        }
        float s0 = 0.f, s1 = 0.f;
#pragma unroll
        for (int nt = 0; nt < 8; nt++) {
#pragma unroll
            for (int j = 0; j < 4; j++) rc[nt][j] = fmaxf(rc[nt][j], MIN_POS);
            s0 += rc[nt][0] + rc[nt][1];
            s1 += rc[nt][2] + rc[nt][3];
        }
        s0 += __shfl_xor_sync(0xffffffffu, s0, 1);
        s0 += __shfl_xor_sync(0xffffffffu, s0, 2);
        s1 += __shfl_xor_sync(0xffffffffu, s1, 1);
        s1 += __shfl_xor_sync(0xffffffffu, s1, 2);

        const size_t ra = (m0 + wm16 + grp) * (size_t)N + n0 + hp * 64;
        const size_t rb = ra + 8 * (size_t)N;

        if (EPI == 6) {
            const float inv0 = 1.f / s0, inv1 = 1.f / s1;
#pragma unroll
            for (int nt = 0; nt < 8; nt++) {
                const int f = nt * 8 + qid * 2;
                *(__half2*)&rh[ra + f] = __floats2half2_rn(rc[nt][0] * inv0, rc[nt][1] * inv0);
                *(__half2*)&rh[rb + f] = __floats2half2_rn(rc[nt][2] * inv1, rc[nt][3] * inv1);
            }
            return;
        }

        // xr = xe*s/rc -> t1s (rows wm16.., cols hp*64.. : warp-disjoint)
#pragma unroll
        for (int nt = 0; nt < 8; nt++) {
            const int f = nt * 8 + qid * 2;
            float2 x0 = __half22float2(*(const __half2*)&xeh[ra + f]);
            float2 x1 = __half22float2(*(const __half2*)&xeh[rb + f]);
            t1s[(wm16 + grp) * 136 + hp * 64 + f]         = hrn(x0.x * s0 / rc[nt][0]);
            t1s[(wm16 + grp) * 136 + hp * 64 + f + 1]     = hrn(x0.y * s0 / rc[nt][1]);
            t1s[(wm16 + grp + 8) * 136 + hp * 64 + f]     = hrn(x1.x * s1 / rc[nt][2]);
            t1s[(wm16 + grp + 8) * 136 + hp * 64 + f + 1] = hrn(x1.y * s1 / rc[nt][3]);
        }
        __syncwarp();

        float uu[8][4];
#pragma unroll
        for (int nt = 0; nt < 8; nt++)
#pragma unroll
            for (int j = 0; j < 4; j++) uu[nt][j] = 0.f;
#pragma unroll
        for (int kk = 0; kk < 64; kk += 16) {
            uint32_t af[4], bf[4][4];
            LDSM4(af[0], af[1], af[2], af[3], aB + (uint32_t)kk * 2);
#pragma unroll
            for (int n2 = 0; n2 < 4; n2++)
                LDSM4(bf[n2][0], bf[n2][1], bf[n2][2], bf[n2][3],
                      sL2 + (uint32_t)((n2 * 16 + bRow2) * 72 + kk) * 2 + bOff);
#pragma unroll
            for (int nt = 0; nt < 8; nt++)
                mma_f16(uu[nt], af, &bf[nt >> 1][(nt & 1) * 2]);
        }
        {
            const size_t eb = (size_t)(n0 + hp * 64) * 256 + m0;
            const int i = wm16 + grp;
#pragma unroll
            for (int nt = 0; nt < 8; nt++) {
                const int g = nt * 8 + qid * 2;
                u1h[eb + (size_t)g * 256 + i]           = hrn(uu[nt][0]);
                u1h[eb + (size_t)(g + 1) * 256 + i]     = hrn(uu[nt][1]);
                u1h[eb + (size_t)g * 256 + i + 8]       = hrn(uu[nt][2]);
                u1h[eb + (size_t)(g + 1) * 256 + i + 8] = hrn(uu[nt][3]);
            }
        }
        return;
    }

    if (EPI == 4) {
        __half* Ts  = (__half*)smb;              // [128][136]
        float* psum = (float*)(smb + 34816);     // [128][4]
        const __half* hIn = (const __half*)res + (size_t)blockIdx.z * sC;
        __half* hOut = aux + (size_t)blockIdx.z * sC;
#pragma unroll
        for (int q = 0; q < 4; q++) {
            int idx = q * 4096 + tid * 8;
            int col = idx >> 7, row = idx & 127;
            *(uint4*)&Ts[col * 136 + row] =
                *(const uint4*)&hIn[(size_t)(n0 + col) * 256 + m0 + row];
        }
        __syncthreads();
#pragma unroll
        for (int mt = 0; mt < 2; mt++) {
            const int row = wm + mt * 16 + grp;
#pragma unroll
            for (int nt = 0; nt < 4; nt++) {
                const int col = wn + nt * 8 + qid * 2;
                float h00 = __half2float(Ts[col * 136 + row]);
                float h01 = __half2float(Ts[(col + 1) * 136 + row]);
                float h10 = __half2float(Ts[col * 136 + row + 8]);
                float h11 = __half2float(Ts[(col + 1) * 136 + row + 8]);
                cfr[mt][nt][0] = fmaxf(cfr[mt][nt][0] * h00, MIN_POS);
                cfr[mt][nt][1] = fmaxf(cfr[mt][nt][1] * h01, MIN_POS);
                cfr[mt][nt][2] = fmaxf(cfr[mt][nt][2] * h10, MIN_POS);
                cfr[mt][nt][3] = fmaxf(cfr[mt][nt][3] * h11, MIN_POS);
            }
        }
        const int p = wid >> 2;
#pragma unroll
        for (int mt = 0; mt < 2; mt++) {
#pragma unroll
            for (int rs = 0; rs < 2; rs++) {
                float s = 0.f;
#pragma unroll
                for (int nt = 0; nt < 4; nt++) s += cfr[mt][nt][rs*2] + cfr[mt][nt][rs*2+1];
                s += __shfl_xor_sync(0xffffffffu, s, 1);
                s += __shfl_xor_sync(0xffffffffu, s, 2);
                int row = wm + mt * 16 + grp + rs * 8;
                if (qid == 0) psum[row * 4 + p] = s;
            }
        }
        __syncthreads();
        const int gc = (wid >> 3) * 2;
#pragma unroll
        for (int mt = 0; mt < 2; mt++) {
            const int rr = wm + mt * 16 + grp;
            float inv0 = 1.f / (psum[rr * 4 + gc]       + psum[rr * 4 + gc + 1]);
            float inv1 = 1.f / (psum[(rr + 8) * 4 + gc] + psum[(rr + 8) * 4 + gc + 1]);
#pragma unroll
            for (int nt = 0; nt < 4; nt++) {
                const int col = wn + nt * 8 + qid * 2;
                Ts[col * 136 + rr]           = hrn(cfr[mt][nt][0] * inv0);
                Ts[(col + 1) * 136 + rr]     = hrn(cfr[mt][nt][1] * inv0);
                Ts[col * 136 + rr + 8]       = hrn(cfr[mt][nt][2] * inv1);
                Ts[(col + 1) * 136 + rr + 8] = hrn(cfr[mt][nt][3] * inv1);
            }
        }
        __syncthreads();
#pragma unroll
        for (int q = 0; q < 4; q++) {
            int idx = q * 4096 + tid * 8;
            int col = idx >> 7, row = idx & 127;
            *(uint4*)&hOut[(size_t)(n0 + col) * 256 + m0 + row] =
                *(const uint4*)&Ts[col * 136 + row];
        }
        return;
    }

    if (EPI == 0) {
        float* psum = (float*)(smb + 34816);     // [128][4]
        const float* biasF = (const float*)bias;
        __half* Ch = (__half*)C;
#pragma unroll
        for (int mt = 0; mt < 2; mt++) {
#pragma unroll
            for (int nt = 0; nt < 4; nt++) {
                const int col = n0 + wn + nt * 8 + qid * 2;
                float2 bv = *(const float2*)&biasF[col];
                cfr[mt][nt][0] = fmaxf(cfr[mt][nt][0] + bv.x, MIN_POS);
                cfr[mt][nt][1] = fmaxf(cfr[mt][nt][1] + bv.y, MIN_POS);
                cfr[mt][nt][2] = fmaxf(cfr[mt][nt][2] + bv.x, MIN_POS);
                cfr[mt][nt][3] = fmaxf(cfr[mt][nt][3] + bv.y, MIN_POS);
            }
        }
        const int p = wid >> 2;
#pragma unroll
        for (int mt = 0; mt < 2; mt++) {
#pragma unroll
            for (int rs = 0; rs < 2; rs++) {
                float s = 0.f;
#pragma unroll
                for (int nt = 0; nt < 4; nt++) s += cfr[mt][nt][rs*2] + cfr[mt][nt][rs*2+1];
                s += __shfl_xor_sync(0xffffffffu, s, 1);
                s += __shfl_xor_sync(0xffffffffu, s, 2);
                int row = wm + mt * 16 + grp + rs * 8;
                if (qid == 0) psum[row * 4 + p] = s;
            }
        }
        __syncthreads();
        const int gc = (wid >> 3) * 2;
#pragma unroll
        for (int mt = 0; mt < 2; mt++) {
            const int rr = wm + mt * 16 + grp;
            const size_t r0 = m0 + rr;
            float inv0 = 1.f / (psum[rr * 4 + gc]       + psum[rr * 4 + gc + 1]);
            float inv1 = 1.f / (psum[(rr + 8) * 4 + gc] + psum[(rr + 8) * 4 + gc + 1]);
#pragma unroll
            for (int nt = 0; nt < 4; nt++) {
                const int col = wn + nt * 8 + qid * 2;
                *(__half2*)&Ch[r0 * N + n0 + col] =
                    __floats2half2_rn(cfr[mt][nt][0] * inv0, cfr[mt][nt][1] * inv0);
                *(__half2*)&Ch[(r0 + 8) * N + n0 + col] =
                    __floats2half2_rn(cfr[mt][nt][2] * inv1, cfr[mt][nt][3] * inv1);
            }
        }
        return;
    }

    // EPI 1 (fp32 out + residual) and EPI 2 (gelu -> fp16)
    const float* biasF = (const float*)bias;
#pragma unroll
    for (int mt = 0; mt < 2; mt++) {
        const size_t r0 = m0 + wm + mt * 16 + grp;
#pragma unroll
        for (int nt = 0; nt < 4; nt++) {
            const int col = n0 + wn + nt * 8 + qid * 2;
            float2 bv = *(const float2*)&biasF[col];
            float v0 = cfr[mt][nt][0] + bv.x, v1 = cfr[mt][nt][1] + bv.y;
            float v2 = cfr[mt][nt][2] + bv.x, v3 = cfr[mt][nt][3] + bv.y;
            if (EPI == 1) {
                const float* resF = (const float*)res;
                float* Cf = (float*)C;
                float2 ra = *(const float2*)&resF[r0 * N + col];
                float2 rb = *(const float2*)&resF[(r0 + 8) * N + col];
                float2 o0; o0.x = v0 + ra.x; o0.y = v1 + ra.y;
                float2 o1; o1.x = v2 + rb.x; o1.y = v3 + rb.y;
                *(float2*)&Cf[r0 * N + col] = o0;
                *(float2*)&Cf[(r0 + 8) * N + col] = o1;
            } else {
                __half* Ch = (__half*)C;
                *(__half2*)&Ch[r0 * N + col] =
                    __floats2half2_rn(gelu_tanh(v0), gelu_tanh(v1));
                *(__half2*)&Ch[(r0 + 8) * N + col] =
                    __floats2half2_rn(gelu_tanh(v2), gelu_tanh(v3));
            }
        }
    }
}

// ---------------- fused prologue: fp16 rounds + both transposes --------------
__global__ __launch_bounds__(256) void prep_kernel(
    const float* __restrict__ ew, const float* __restrict__ ow,
    const float* __restrict__ w1, const float* __restrict__ w2,
    const float* __restrict__ gw, const float* __restrict__ lw,
    const float* __restrict__ h0,
    __half* __restrict__ ewH, __half* __restrict__ owH,
    __half* __restrict__ w1H, __half* __restrict__ w2H,
    __half* __restrict__ gwH, __half* __restrict__ lwH,
    __half* __restrict__ gwTH, __half* __restrict__ hT16)
{
    __shared__ float t[32][33];
    const int b = blockIdx.x, tid = threadIdx.x;
    if (b < 2628) {
        int i = b * 256 + tid;
        if (i >= 672768) return;
        const float* in; __half* out; int off;
        if (i < 65536)        { in = ew; out = ewH; off = i; }
        else if (i < 131072)  { in = ow; out = owH; off = i - 65536; }
        else if (i < 393216)  { in = w1; out = w1H; off = i - 131072; }
        else if (i < 655360)  { in = w2; out = w2H; off = i - 393216; }
        else if (i < 671744)  { in = gw; out = gwH; off = i - 655360; }
        else                  { in = lw; out = lwH; off = i - 671744; }
        float4 v = *(const float4*)&in[(size_t)off * 4];
        *(__half2*)&out[(size_t)off * 4]     = __floats2half2_rn(v.x, v.y);
        *(__half2*)&out[(size_t)off * 4 + 2] = __floats2half2_rn(v.z, v.w);
        return;
    }
    const int lx = tid & 31, ly = tid >> 5;
    if (b < 2692) {
        int bb = b - 2628;
        int c0 = (bb & 7) * 32, r0 = (bb >> 3) * 32;
#pragma unroll
        for (int i = 0; i < 32; i += 8)
            t[ly + i][lx] = gw[(size_t)(r0 + ly + i) * 256 + c0 + lx];
        __syncthreads();
#pragma unroll
        for (int i = 0; i < 32; i += 8)
            gwTH[(size_t)(c0 + ly + i) * 256 + r0 + lx] = hrn(t[lx][ly + i]);
        return;
    }
    {
        int bb = b - 2692;
        int bz = bb >> 7, rem = bb & 127;
        int c0 = (rem & 15) * 32, r0 = (rem >> 4) * 32;
        const float* in = h0 + (size_t)bz * 256 * 512;
        __half* out = hT16 + (size_t)bz * 256 * 512;
#pragma unroll
        for (int i = 0; i < 32; i += 8)
            t[ly + i][lx] = in[(size_t)(r0 + ly + i) * 512 + c0 + lx];
        __syncthreads();
#pragma unroll
        for (int i = 0; i < 32; i += 8)
            out[(size_t)(c0 + ly + i) * 256 + r0 + lx] = hrn(t[lx][ly + i]);
    }
}

// ---------------- LayerNorm (fp32 in -> fp16 out) ----------------------------
__global__ __launch_bounds__(256) void ln_kernel(
    const float* __restrict__ x, const float* __restrict__ g,
    const float* __restrict__ b, __half* __restrict__ out)
{
    int row  = blockIdx.x * 8 + (threadIdx.x >> 5);
    int lane = threadIdx.x & 31;
    const float* xr = x + (size_t)row * 512;
    float4 v[4];
    float s = 0.f, sq = 0.f;
#pragma unroll
    for (int w = 0; w < 4; w++) {
        v[w] = *(const float4*)&xr[w * 128 + lane * 4];
        s  += v[w].x + v[w].y + v[w].z + v[w].w;
        sq += v[w].x*v[w].x + v[w].y*v[w].y + v[w].z*v[w].z + v[w].w*v[w].w;
    }
#pragma unroll
    for (int off = 16; off > 0; off >>= 1) {
        s  += __shfl_xor_sync(0xffffffffu, s,  off);
        sq += __shfl_xor_sync(0xffffffffu, sq, off);
    }
    float mu = s * (1.f / 512.f);
    float var = sq * (1.f / 512.f) - mu * mu;
    float rstd = rsqrtf(var + 1e-5f);
    __half* orow = out + (size_t)row * 512;
#pragma unroll
    for (int w = 0; w < 4; w++) {
        int c = w * 128 + lane * 4;
        float4 gv = *(const float4*)&g[c];
        float4 bv = *(const float4*)&b[c];
        *(__half2*)&orow[c] = __floats2half2_rn(
            (v[w].x - mu) * rstd * gv.x + bv.x, (v[w].y - mu) * rstd * gv.y + bv.y);
        *(__half2*)&orow[c + 2] = __floats2half2_rn(
            (v[w].z - mu) * rstd * gv.z + bv.z, (v[w].w - mu) * rstd * gv.w + bv.w);
    }
}

// ---------------- host launcher -----------------------------------------------
extern "C" void kernel_launch(void* const* d_in, const int* in_sizes, int n_in,
                              void* d_out, int out_size)
{
    const float* x    = (const float*)d_in[0];
    const float* ew   = (const float*)d_in[1];
    const float* eb   = (const float*)d_in[2];
    const float* lw   = (const float*)d_in[3];
    const float* gw   = (const float*)d_in[4];
    const float* ow   = (const float*)d_in[5];
    const float* ob   = (const float*)d_in[6];
    const float* ln1g = (const float*)d_in[7];
    const float* ln1b = (const float*)d_in[8];
    const float* ln2g = (const float*)d_in[9];
    const float* ln2b = (const float*)d_in[10];
    const float* w1   = (const float*)d_in[11];
    const float* b1   = (const float*)d_in[12];
    const float* w2   = (const float*)d_in[13];
    const float* b2   = (const float*)d_in[14];
    const float* h0   = (const float*)d_in[15];
    float* out = (float*)d_out;

    float* xres;
    __half *xn, *xe, *hT, *u1T, *r, *mlp, *gwH, *gwTH, *ewH, *owH, *w1H, *w2H, *lwH;
    cudaGetSymbolAddress((void**)&xres, g_xres);
    cudaGetSymbolAddress((void**)&xn,   g_xn16);
    cudaGetSymbolAddress((void**)&xe,   g_xe16);
    cudaGetSymbolAddress((void**)&hT,   g_hT16);
    cudaGetSymbolAddress((void**)&u1T,  g_u1T16);
    cudaGetSymbolAddress((void**)&r,    g_r16);
    cudaGetSymbolAddress((void**)&mlp,  g_mlp16);
    cudaGetSymbolAddress((void**)&gwH,  g_gwH);
    cudaGetSymbolAddress((void**)&gwTH, g_gwTH);
    cudaGetSymbolAddress((void**)&ewH,  g_ewH);
    cudaGetSymbolAddress((void**)&owH,  g_owH);
    cudaGetSymbolAddress((void**)&w1H,  g_w1H);
    cudaGetSymbolAddress((void**)&w2H,  g_w2H);
    cudaGetSymbolAddress((void**)&lwH,  g_lwH);

    cudaFuncSetAttribute(mma_gemm<0>, cudaFuncAttributeMaxDynamicSharedMemorySize, MM_SMEM);
    cudaFuncSetAttribute(mma_gemm<1>, cudaFuncAttributeMaxDynamicSharedMemorySize, MM_SMEM);
    cudaFuncSetAttribute(mma_gemm<2>, cudaFuncAttributeMaxDynamicSharedMemorySize, MM_SMEM);
    cudaFuncSetAttribute(mma_gemm<4>, cudaFuncAttributeMaxDynamicSharedMemorySize, MM_SMEM);
    cudaFuncSetAttribute(mma_gemm<5>, cudaFuncAttributeMaxDynamicSharedMemorySize, MM_SMEM);
    cudaFuncSetAttribute(mma_gemm<6>, cudaFuncAttributeMaxDynamicSharedMemorySize, MM_SMEM);

    const long long SB = 512LL * 256;
    const long long SC = 256LL * 512;

    prep_kernel<<<19076, 256>>>(ew, ow, w1, w2, gw, lw, h0,
                                ewH, owH, w1H, w2H, gwH, lwH, gwTH, hT);
    ln_kernel<<<BSROWS / 8, 256>>>(x, ln1g, ln1b, xn);
    mma_gemm<0><<<dim3(4, 256, 1), 512, MM_SMEM>>>(xn, ewH, eb, nullptr, xe, nullptr, 512, 512, 0, 0);

    for (int it = 0; it < 10; it++) {
        if (it < 9) {
            mma_gemm<5><<<dim3(4, 2, 128), 512, MM_SMEM>>>(gwTH, hT, lwH, xe, r, u1T, 256, 512, SB, SC);
            mma_gemm<4><<<dim3(4, 2, 128), 512, MM_SMEM>>>(gwH, u1T, nullptr, hT, hT, hT, 256, 512, SB, SC);
        } else {
            mma_gemm<6><<<dim3(4, 2, 128), 512, MM_SMEM>>>(gwTH, hT, lwH, xe, r, u1T, 256, 512, SB, SC);
        }
    }

    mma_gemm<1><<<dim3(4, 256, 1), 512, MM_SMEM>>>(r, owH, ob, x, xres, nullptr, 512, 512, 0, 0);
    ln_kernel<<<BSROWS / 8, 256>>>(xres, ln2g, ln2b, xn);
    mma_gemm<2><<<dim3(16, 256, 1), 512, MM_SMEM>>>(xn, w1H, b1, nullptr, mlp, nullptr, 512, 2048, 0, 0);
    mma_gemm<1><<<dim3(4, 256, 1), 512, MM_SMEM>>>(mlp, w2H, b2, xres, out, nullptr, 2048, 512, 0, 0);
}

// round 16
// speedup vs baseline: 1.6634x; 1.0116x over previous
#include <cuda_runtime.h>
#include <cuda_fp16.h>
#include <cstdint>

#define BSZ   128
#define SEQ   256
#define FDIM  512
#define EDIM  512
#define HEADS 8
#define BSROWS (BSZ*SEQ)
#define MLPD  2048
#define MIN_POS 1e-6f

__device__ float g_xres[(size_t)BSROWS*FDIM];
__device__ __align__(16) __half g_xn16 [(size_t)BSROWS*FDIM];
__device__ __align__(16) __half g_xe16 [(size_t)BSROWS*EDIM];
__device__ __align__(16) __half g_hT16 [(size_t)BSROWS*EDIM];
__device__ __align__(16) __half g_u1T16[(size_t)BSROWS*EDIM];
__device__ __align__(16) __half g_r16  [(size_t)BSROWS*EDIM];
__device__ __align__(16) __half g_mlp16[(size_t)BSROWS*MLPD];
__device__ __align__(16) __half g_gwH  [(size_t)SEQ*SEQ];
__device__ __align__(16) __half g_gwTH [(size_t)SEQ*SEQ];
__device__ __align__(16) __half g_ewH  [(size_t)EDIM*FDIM];
__device__ __align__(16) __half g_owH  [(size_t)FDIM*EDIM];
__device__ __align__(16) __half g_w1H  [(size_t)MLPD*FDIM];
__device__ __align__(16) __half g_w2H  [(size_t)FDIM*MLPD];
__device__ __align__(16) __half g_lwH  [64*64];

// ---------------- helpers -----------------------------------------------------
__device__ __forceinline__ __half hrn(float x) { return __float2half_rn(x); }
#define CP16(dst, src) \
    asm volatile("cp.async.cg.shared.global [%0], [%1], 16;" :: "r"(dst), "l"(src))
#define CP_COMMIT() asm volatile("cp.async.commit_group;" ::: "memory")
#define CP_WAIT(n)  asm volatile("cp.async.wait_group %0;" :: "n"(n) : "memory")
#define L2PF(p) asm volatile("prefetch.global.L2 [%0];" :: "l"(p))
#define LDSM4(r0, r1, r2, r3, addr) \
    asm volatile("ldmatrix.sync.aligned.m8n8.x4.shared.b16 {%0,%1,%2,%3}, [%4];" \
                 : "=r"(r0), "=r"(r1), "=r"(r2), "=r"(r3) : "r"(addr))
__device__ __forceinline__ uint32_t s2u(const void* p) {
    uint32_t a;
    asm("{ .reg .u64 t; cvta.to.shared.u64 t, %1; cvt.u32.u64 %0, t; }" : "=r"(a) : "l"(p));
    return a;
}
__device__ __forceinline__ void mma_f16(float* c, const uint32_t* a, const uint32_t* b) {
    asm volatile(
        "mma.sync.aligned.m16n8k16.row.col.f32.f16.f16.f32 "
        "{%0,%1,%2,%3}, {%4,%5,%6,%7}, {%8,%9}, {%0,%1,%2,%3};"
        : "+f"(c[0]), "+f"(c[1]), "+f"(c[2]), "+f"(c[3])
        : "r"(a[0]), "r"(a[1]), "r"(a[2]), "r"(a[3]), "r"(b[0]), "r"(b[1]));
}
static __device__ __forceinline__ float gelu_tanh(float v) {
    float t = tanhf(0.7978845608028654f * (v + 0.044715f * v * v * v));
    return 0.5f * v * (1.f + t);
}

// ---------------- fp16 mma GEMM: C[M,N]=A[M,K]@B[N,K]^T ----------------------
// 128x128 tile, 512 threads (4x4 warps, 32x32 warp tile), K-chunk 64 fp16,
// 3-stage cp.async ring (1 barrier per 64-K chunk), ldmatrix b16, fp32 accum.
// EPI: 0=bias+clip+L1norm64->fp16  1=bias+res->fp32  2=bias+gelu->fp16
//      4=fused NNMF-B in-place on hT16  5=fused NNMF-A  6=NNMF-A last (r only)
#define SMPH 72                 // fp16 row stride (144 B)
#define STGB 18432              // bytes per operand per stage (128*144)
#define MM_SMEM 110592          // 3 stages x 2 operands

template <int EPI>
__global__ __launch_bounds__(512, 2) void mma_gemm(
    const __half* __restrict__ A, const __half* __restrict__ B,
    const void* __restrict__ bias, const void* __restrict__ res,
    void* __restrict__ C, __half* __restrict__ aux, int K, int N,
    long long sB, long long sC)
{
    extern __shared__ char smb[];
    const int tid = threadIdx.x, wid = tid >> 5, lane = tid & 31;
    const int grp = lane >> 2, qid = lane & 3;
    const int n0 = blockIdx.x * 128;
    const size_t m0 = (size_t)blockIdx.y * 128;
    B += (size_t)blockIdx.z * sB;
    const int wm = (wid & 3) * 32, wn = (wid >> 2) * 32;
    const uint32_t sAu = s2u(smb);

    const int t8 = lane >> 3, r8 = lane & 7;
    const int rowA = wm + (t8 & 1) * 8 + r8;
    const int segA = (t8 >> 1) * 8;
    const int rowB = wn + (t8 >> 1) * 8 + r8;
    const int segB = (t8 & 1) * 8;

    auto load_chunk = [&](int st, int kt) {
        uint32_t base = sAu + (uint32_t)(st * 2 * STGB);
#pragma unroll
        for (int i = 0; i < 2; i++) {
            int id = tid + 512 * i;
            int row = id >> 3, sg = id & 7;
            CP16(base + (uint32_t)(row * 144 + sg * 16),
                 &A[(m0 + row) * K + kt + sg * 8]);
            CP16(base + STGB + (uint32_t)(row * 144 + sg * 16),
                 &B[(size_t)(n0 + row) * K + kt + sg * 8]);
        }
        CP_COMMIT();
    };

    float cfr[2][4][4];
#pragma unroll
    for (int mt = 0; mt < 2; mt++)
#pragma unroll
        for (int nt = 0; nt < 4; nt++)
#pragma unroll
            for (int i = 0; i < 4; i++) cfr[mt][nt][i] = 0.f;

    const int nch = K >> 6;
    load_chunk(0, 0);
    if (nch > 1) load_chunk(1, 64);

    if (EPI == 5) {
        const __half* xh = (const __half*)res;
        if (tid < 256) {
            int row = tid >> 1, l = tid & 1;
            L2PF(&xh[(m0 + row) * (size_t)N + n0 + l * 64]);
        }
        if (tid < 64) L2PF(&((const __half*)bias)[tid * 64]);
    } else if (EPI == 4) {
        const __half* hh = (const __half*)res;
        if (tid < 256) {
            int col = tid >> 1, l = tid & 1;
            L2PF(&hh[((size_t)blockIdx.z * sC) + (size_t)(n0 + col) * 256 + m0 + l * 64]);
        }
    }

    for (int c = 0; c < nch; c++) {
        if (c + 1 < nch) CP_WAIT(1);
        else             CP_WAIT(0);
        __syncthreads();
        if (c + 2 < nch) load_chunk((c + 2) % 3, (c + 2) * 64);
        const uint32_t sAs = sAu + (uint32_t)((c % 3) * 2 * STGB);
        const uint32_t sBs = sAs + STGB;
#pragma unroll
        for (int kk = 0; kk < 64; kk += 16) {
            uint32_t af[2][4], bf[2][4];
#pragma unroll
            for (int mt = 0; mt < 2; mt++)
                LDSM4(af[mt][0], af[mt][1], af[mt][2], af[mt][3],
                      sAs + (uint32_t)((rowA + mt * 16) * SMPH + kk + segA) * 2);
#pragma unroll
            for (int ntp = 0; ntp < 2; ntp++)
                LDSM4(bf[ntp][0], bf[ntp][1], bf[ntp][2], bf[ntp][3],
                      sBs + (uint32_t)((rowB + ntp * 16) * SMPH + kk + segB) * 2);
#pragma unroll
            for (int mt = 0; mt < 2; mt++)
#pragma unroll
                for (int nt = 0; nt < 4; nt++)
                    mma_f16(cfr[mt][nt], af[mt], &bf[nt >> 1][(nt & 1) * 2]);
        }
    }
    __syncthreads();

    if (EPI == 5 || EPI == 6) {
        __half* t1s = (__half*)smb;              // [128][136]
        __half* lwT = (__half*)(smb + 34816);    // [64][72]
        __half* lwS = (__half*)(smb + 44032);    // [64][72]
        const uint32_t sT = sAu, sL1 = sAu + 34816, sL2 = sAu + 44032;
        const __half* lwh = (const __half*)bias;
        const __half* xeh = (const __half*)res + (size_t)blockIdx.z * sC;
        __half* rh = (__half*)C + (size_t)blockIdx.z * sC;
        __half* u1h = aux + (size_t)blockIdx.z * sC;
#pragma unroll
        for (int q = 0; q < 8; q++) {
            int idx = q * 512 + tid;
            int g = idx >> 6, f = idx & 63;
            __half v = lwh[idx];
            lwT[f * 72 + g] = v;
            lwS[g * 72 + f] = v;
        }
#pragma unroll
        for (int mt = 0; mt < 2; mt++) {
            const int row = wm + mt * 16 + grp;
#pragma unroll
            for (int nt = 0; nt < 4; nt++) {
                const int col = wn + nt * 8 + qid * 2;
                t1s[row * 136 + col]           = hrn(cfr[mt][nt][0]);
                t1s[row * 136 + col + 1]       = hrn(cfr[mt][nt][1]);
                t1s[(row + 8) * 136 + col]     = hrn(cfr[mt][nt][2]);
                t1s[(row + 8) * 136 + col + 1] = hrn(cfr[mt][nt][3]);
            }
        }
        __syncthreads();

        // warps 0-7: hp=0 (cols 0-63); warps 8-15: hp=1 (cols 64-127)
        const int hp = wid >> 3, wm16 = (wid & 7) * 16;
        const uint32_t aB = sT + (uint32_t)((wm16 + (t8 & 1) * 8 + r8) * 136 + (t8 >> 1) * 8 + hp * 64) * 2;
        const int bRow2 = (t8 >> 1) * 8 + r8;
        const uint32_t bOff = (uint32_t)((t8 & 1) * 8) * 2;

        float rc[8][4];
#pragma unroll
        for (int nt = 0; nt < 8; nt++)
#pragma unroll
            for (int j = 0; j < 4; j++) rc[nt][j] = 0.f;
#pragma unroll
        for (int kk = 0; kk < 64; kk += 16) {
            uint32_t af[4], bf[4][4];
            LDSM4(af[0], af[1], af[2], af[3], aB + (uint32_t)kk * 2);
#pragma unroll
            for (int n2 = 0; n2 < 4; n2++)
                LDSM4(bf[n2][0], bf[n2][1], bf[n2][2], bf[n2][3],
                      sL1 + (uint32_t)((n2 * 16 + bRow2) * 72 + kk) * 2 + bOff);
#pragma unroll
            for (int nt = 0; nt < 8; nt++)
                mma_f16(rc[nt], af, &bf[nt >> 1][(nt & 1) * 2]);
        }
        float s0 = 0.f, s1 = 0.f;
#pragma unroll
        for (int nt = 0; nt < 8; nt++) {
#pragma unroll
            for (int j = 0; j < 4; j++) rc[nt][j] = fmaxf(rc[nt][j], MIN_POS);
            s0 += rc[nt][0] + rc[nt][1];
            s1 += rc[nt][2] + rc[nt][3];
        }
        s0 += __shfl_xor_sync(0xffffffffu, s0, 1);
        s0 += __shfl_xor_sync(0xffffffffu, s0, 2);
        s1 += __shfl_xor_sync(0xffffffffu, s1, 1);
        s1 += __shfl_xor_sync(0xffffffffu, s1, 2);

        const size_t ra = (m0 + wm16 + grp) * (size_t)N + n0 + hp * 64;
        const size_t rb = ra + 8 * (size_t)N;

        if (EPI == 6) {
            const float inv0 = 1.f / s0, inv1 = 1.f / s1;
#pragma unroll
            for (int nt = 0; nt < 8; nt++) {
                const int f = nt * 8 + qid * 2;
                *(__half2*)&rh[ra + f] = __floats2half2_rn(rc[nt][0] * inv0, rc[nt][1] * inv0);
                *(__half2*)&rh[rb + f] = __floats2half2_rn(rc[nt][2] * inv1, rc[nt][3] * inv1);
            }
            return;
        }

#pragma unroll
        for (int nt = 0; nt < 8; nt++) {
            const int f = nt * 8 + qid * 2;
            float2 x0 = __half22float2(*(const __half2*)&xeh[ra + f]);
            float2 x1 = __half22float2(*(const __half2*)&xeh[rb + f]);
            t1s[(wm16 + grp) * 136 + hp * 64 + f]         = hrn(x0.x * s0 / rc[nt][0]);
            t1s[(wm16 + grp) * 136 + hp * 64 + f + 1]     = hrn(x0.y * s0 / rc[nt][1]);
            t1s[(wm16 + grp + 8) * 136 + hp * 64 + f]     = hrn(x1.x * s1 / rc[nt][2]);
            t1s[(wm16 + grp + 8) * 136 + hp * 64 + f + 1] = hrn(x1.y * s1 / rc[nt][3]);
        }
        __syncwarp();

        float uu[8][4];
#pragma unroll
        for (int nt = 0; nt < 8; nt++)
#pragma unroll
            for (int j = 0; j < 4; j++) uu[nt][j] = 0.f;
#pragma unroll
        for (int kk = 0; kk < 64; kk += 16) {
            uint32_t af[4], bf[4][4];
            LDSM4(af[0], af[1], af[2], af[3], aB + (uint32_t)kk * 2);
#pragma unroll
            for (int n2 = 0; n2 < 4; n2++)
                LDSM4(bf[n2][0], bf[n2][1], bf[n2][2], bf[n2][3],
                      sL2 + (uint32_t)((n2 * 16 + bRow2) * 72 + kk) * 2 + bOff);
#pragma unroll
            for (int nt = 0; nt < 8; nt++)
                mma_f16(uu[nt], af, &bf[nt >> 1][(nt & 1) * 2]);
        }
        {
            const size_t eb = (size_t)(n0 + hp * 64) * 256 + m0;
            const int i = wm16 + grp;
#pragma unroll
            for (int nt = 0; nt < 8; nt++) {
                const int g = nt * 8 + qid * 2;
                u1h[eb + (size_t)g * 256 + i]           = hrn(uu[nt][0]);
                u1h[eb + (size_t)(g + 1) * 256 + i]     = hrn(uu[nt][1]);
                u1h[eb + (size_t)g * 256 + i + 8]       = hrn(uu[nt][2]);
                u1h[eb + (size_t)(g + 1) * 256 + i + 8] = hrn(uu[nt][3]);
            }
        }
        return;
    }

    if (EPI == 4) {
        __half* Ts  = (__half*)smb;              // [128][136]
        float* psum = (float*)(smb + 34816);     // [128][4]
        const __half* hIn = (const __half*)res + (size_t)blockIdx.z * sC;
        __half* hOut = aux + (size_t)blockIdx.z * sC;
#pragma unroll
        for (int q = 0; q < 4; q++) {
            int idx = q * 4096 + tid * 8;
            int col = idx >> 7, row = idx & 127;
            *(uint4*)&Ts[col * 136 + row] =
                *(const uint4*)&hIn[(size_t)(n0 + col) * 256 + m0 + row];
        }
        __syncthreads();
#pragma unroll
        for (int mt = 0; mt < 2; mt++) {
            const int row = wm + mt * 16 + grp;
#pragma unroll
            for (int nt = 0; nt < 4; nt++) {
                const int col = wn + nt * 8 + qid * 2;
                float h00 = __half2float(Ts[col * 136 + row]);
                float h01 = __half2float(Ts[(col + 1) * 136 + row]);
                float h10 = __half2float(Ts[col * 136 + row + 8]);
                float h11 = __half2float(Ts[(col + 1) * 136 + row + 8]);
                cfr[mt][nt][0] = fmaxf(cfr[mt][nt][0] * h00, MIN_POS);
                cfr[mt][nt][1] = fmaxf(cfr[mt][nt][1] * h01, MIN_POS);
                cfr[mt][nt][2] = fmaxf(cfr[mt][nt][2] * h10, MIN_POS);
                cfr[mt][nt][3] = fmaxf(cfr[mt][nt][3] * h11, MIN_POS);
            }
        }
        const int p = wid >> 2;
#pragma unroll
        for (int mt = 0; mt < 2; mt++) {
#pragma unroll
            for (int rs = 0; rs < 2; rs++) {
                float s = 0.f;
#pragma unroll
                for (int nt = 0; nt < 4; nt++) s += cfr[mt][nt][rs*2] + cfr[mt][nt][rs*2+1];
                s += __shfl_xor_sync(0xffffffffu, s, 1);
                s += __shfl_xor_sync(0xffffffffu, s, 2);
                int row = wm + mt * 16 + grp + rs * 8;
                if (qid == 0) psum[row * 4 + p] = s;
            }
        }
        __syncthreads();
        const int gc = (wid >> 3) * 2;
#pragma unroll
        for (int mt = 0; mt < 2; mt++) {
            const int rr = wm + mt * 16 + grp;
            float inv0 = 1.f / (psum[rr * 4 + gc]       + psum[rr * 4 + gc + 1]);
            float inv1 = 1.f / (psum[(rr + 8) * 4 + gc] + psum[(rr + 8) * 4 + gc + 1]);
#pragma unroll
            for (int nt = 0; nt < 4; nt++) {
                const int col = wn + nt * 8 + qid * 2;
                Ts[col * 136 + rr]           = hrn(cfr[mt][nt][0] * inv0);
                Ts[(col + 1) * 136 + rr]     = hrn(cfr[mt][nt][1] * inv0);
                Ts[col * 136 + rr + 8]       = hrn(cfr[mt][nt][2] * inv1);
                Ts[(col + 1) * 136 + rr + 8] = hrn(cfr[mt][nt][3] * inv1);
            }
        }
        __syncthreads();
#pragma unroll
        for (int q = 0; q < 4; q++) {
            int idx = q * 4096 + tid * 8;
            int col = idx >> 7, row = idx & 127;
            *(uint4*)&hOut[(size_t)(n0 + col) * 256 + m0 + row] =
                *(const uint4*)&Ts[col * 136 + row];
        }
        return;
    }

    if (EPI == 0) {
        float* psum = (float*)(smb + 34816);     // [128][4]
        const float* biasF = (const float*)bias;
        __half* Ch = (__half*)C;
#pragma unroll
        for (int mt = 0; mt < 2; mt++) {
#pragma unroll
            for (int nt = 0; nt < 4; nt++) {
                const int col = n0 + wn + nt * 8 + qid * 2;
                float2 bv = *(const float2*)&biasF[col];
                cfr[mt][nt][0] = fmaxf(cfr[mt][nt][0] + bv.x, MIN_POS);
                cfr[mt][nt][1] = fmaxf(cfr[mt][nt][1] + bv.y, MIN_POS);
                cfr[mt][nt][2] = fmaxf(cfr[mt][nt][2] + bv.x, MIN_POS);
                cfr[mt][nt][3] = fmaxf(cfr[mt][nt][3] + bv.y, MIN_POS);
            }
        }
        const int p = wid >> 2;
#pragma unroll
        for (int mt = 0; mt < 2; mt++) {
#pragma unroll
            for (int rs = 0; rs < 2; rs++) {
                float s = 0.f;
#pragma unroll
                for (int nt = 0; nt < 4; nt++) s += cfr[mt][nt][rs*2] + cfr[mt][nt][rs*2+1];
                s += __shfl_xor_sync(0xffffffffu, s, 1);
                s += __shfl_xor_sync(0xffffffffu, s, 2);
                int row = wm + mt * 16 + grp + rs * 8;
                if (qid == 0) psum[row * 4 + p] = s;
            }
        }
        __syncthreads();
        const int gc = (wid >> 3) * 2;
#pragma unroll
        for (int mt = 0; mt < 2; mt++) {
            const int rr = wm + mt * 16 + grp;
            const size_t r0 = m0 + rr;
            float inv0 = 1.f / (psum[rr * 4 + gc]       + psum[rr * 4 + gc + 1]);
            float inv1 = 1.f / (psum[(rr + 8) * 4 + gc] + psum[(rr + 8) * 4 + gc + 1]);
#pragma unroll
            for (int nt = 0; nt < 4; nt++) {
                const int col = wn + nt * 8 + qid * 2;
                *(__half2*)&Ch[r0 * N + n0 + col] =
                    __floats2half2_rn(cfr[mt][nt][0] * inv0, cfr[mt][nt][1] * inv0);
                *(__half2*)&Ch[(r0 + 8) * N + n0 + col] =
                    __floats2half2_rn(cfr[mt][nt][2] * inv1, cfr[mt][nt][3] * inv1);
            }
        }
        return;
    }

    // EPI 1 (fp32 out + residual) and EPI 2 (gelu -> fp16)
    const float* biasF = (const float*)bias;
#pragma unroll
    for (int mt = 0; mt < 2; mt++) {
        const size_t r0 = m0 + wm + mt * 16 + grp;
#pragma unroll
        for (int nt = 0; nt < 4; nt++) {
            const int col = n0 + wn + nt * 8 + qid * 2;
            float2 bv = *(const float2*)&biasF[col];
            float v0 = cfr[mt][nt][0] + bv.x, v1 = cfr[mt][nt][1] + bv.y;
            float v2 = cfr[mt][nt][2] + bv.x, v3 = cfr[mt][nt][3] + bv.y;
            if (EPI == 1) {
                const float* resF = (const float*)res;
                float* Cf = (float*)C;
                float2 ra = *(const float2*)&resF[r0 * N + col];
                float2 rb = *(const float2*)&resF[(r0 + 8) * N + col];
                float2 o0; o0.x = v0 + ra.x; o0.y = v1 + ra.y;
                float2 o1; o1.x = v2 + rb.x; o1.y = v3 + rb.y;
                *(float2*)&Cf[r0 * N + col] = o0;
                *(float2*)&Cf[(r0 + 8) * N + col] = o1;
            } else {
                __half* Ch = (__half*)C;
                *(__half2*)&Ch[r0 * N + col] =
                    __floats2half2_rn(gelu_tanh(v0), gelu_tanh(v1));
                *(__half2*)&Ch[(r0 + 8) * N + col] =
                    __floats2half2_rn(gelu_tanh(v2), gelu_tanh(v3));
            }
        }
    }
}

// ---------------- fused prologue: fp16 rounds + both transposes --------------
__global__ __launch_bounds__(256) void prep_kernel(
    const float* __restrict__ ew, const float* __restrict__ ow,
    const float* __restrict__ w1, const float* __restrict__ w2,
    const float* __restrict__ gw, const float* __restrict__ lw,
    const float* __restrict__ h0,
    __half* __restrict__ ewH, __half* __restrict__ owH,
    __half* __restrict__ w1H, __half* __restrict__ w2H,
    __half* __restrict__ gwH, __half* __restrict__ lwH,
    __half* __restrict__ gwTH, __half* __restrict__ hT16)
{
    __shared__ float t[32][33];
    const int b = blockIdx.x, tid = threadIdx.x;
    if (b < 2628) {
        int i = b * 256 + tid;
        if (i >= 672768) return;
        const float* in; __half* out; int off;
        if (i < 65536)        { in = ew; out = ewH; off = i; }
        else if (i < 131072)  { in = ow; out = owH; off = i - 65536; }
        else if (i < 393216)  { in = w1; out = w1H; off = i - 131072; }
        else if (i < 655360)  { in = w2; out = w2H; off = i - 393216; }
        else if (i < 671744)  { in = gw; out = gwH; off = i - 655360; }
        else                  { in = lw; out = lwH; off = i - 671744; }
        float4 v = *(const float4*)&in[(size_t)off * 4];
        *(__half2*)&out[(size_t)off * 4]     = __floats2half2_rn(v.x, v.y);
        *(__half2*)&out[(size_t)off * 4 + 2] = __floats2half2_rn(v.z, v.w);
        return;
    }
    const int lx = tid & 31, ly = tid >> 5;
    if (b < 2692) {
        int bb = b - 2628;
        int c0 = (bb & 7) * 32, r0 = (bb >> 3) * 32;
#pragma unroll
        for (int i = 0; i < 32; i += 8)
            t[ly + i][lx] = gw[(size_t)(r0 + ly + i) * 256 + c0 + lx];
        __syncthreads();
#pragma unroll
        for (int i = 0; i < 32; i += 8)
            gwTH[(size_t)(c0 + ly + i) * 256 + r0 + lx] = hrn(t[lx][ly + i]);
        return;
    }
    {
        int bb = b - 2692;
        int bz = bb >> 7, rem = bb & 127;
        int c0 = (rem & 15) * 32, r0 = (rem >> 4) * 32;
        const float* in = h0 + (size_t)bz * 256 * 512;
        __half* out = hT16 + (size_t)bz * 256 * 512;
#pragma unroll
        for (int i = 0; i < 32; i += 8)
            t[ly + i][lx] = in[(size_t)(r0 + ly + i) * 512 + c0 + lx];
        __syncthreads();
#pragma unroll
        for (int i = 0; i < 32; i += 8)
            out[(size_t)(c0 + ly + i) * 256 + r0 + lx] = hrn(t[lx][ly + i]);
    }
}

// ---------------- LayerNorm (fp32 in -> fp16 out) ----------------------------
__global__ __launch_bounds__(256) void ln_kernel(
    const float* __restrict__ x, const float* __restrict__ g,
    const float* __restrict__ b, __half* __restrict__ out)
{
    int row  = blockIdx.x * 8 + (threadIdx.x >> 5);
    int lane = threadIdx.x & 31;
    const float* xr = x + (size_t)row * 512;
    float4 v[4];
    float s = 0.f, sq = 0.f;
#pragma unroll
    for (int w = 0; w < 4; w++) {
        v[w] = *(const float4*)&xr[w * 128 + lane * 4];
        s  += v[w].x + v[w].y + v[w].z + v[w].w;
        sq += v[w].x*v[w].x + v[w].y*v[w].y + v[w].z*v[w].z + v[w].w*v[w].w;
    }
#pragma unroll
    for (int off = 16; off > 0; off >>= 1) {
        s  += __shfl_xor_sync(0xffffffffu, s,  off);
        sq += __shfl_xor_sync(0xffffffffu, sq, off);
    }
    float mu = s * (1.f / 512.f);
    float var = sq * (1.f / 512.f) - mu * mu;
    float rstd = rsqrtf(var + 1e-5f);
    __half* orow = out + (size_t)row * 512;
#pragma unroll
    for (int w = 0; w < 4; w++) {
        int c = w * 128 + lane * 4;
        float4 gv = *(const float4*)&g[c];
        float4 bv = *(const float4*)&b[c];
        *(__half2*)&orow[c] = __floats2half2_rn(
            (v[w].x - mu) * rstd * gv.x + bv.x, (v[w].y - mu) * rstd * gv.y + bv.y);
        *(__half2*)&orow[c + 2] = __floats2half2_rn(
            (v[w].z - mu) * rstd * gv.z + bv.z, (v[w].w - mu) * rstd * gv.w + bv.w);
    }
}

// ---------------- host launcher -----------------------------------------------
extern "C" void kernel_launch(void* const* d_in, const int* in_sizes, int n_in,
                              void* d_out, int out_size)
{
    const float* x    = (const float*)d_in[0];
    const float* ew   = (const float*)d_in[1];
    const float* eb   = (const float*)d_in[2];
    const float* lw   = (const float*)d_in[3];
    const float* gw   = (const float*)d_in[4];
    const float* ow   = (const float*)d_in[5];
    const float* ob   = (const float*)d_in[6];
    const float* ln1g = (const float*)d_in[7];
    const float* ln1b = (const float*)d_in[8];
    const float* ln2g = (const float*)d_in[9];
    const float* ln2b = (const float*)d_in[10];
    const float* w1   = (const float*)d_in[11];
    const float* b1   = (const float*)d_in[12];
    const float* w2   = (const float*)d_in[13];
    const float* b2   = (const float*)d_in[14];
    const float* h0   = (const float*)d_in[15];
    float* out = (float*)d_out;

    float* xres;
    __half *xn, *xe, *hT, *u1T, *r, *mlp, *gwH, *gwTH, *ewH, *owH, *w1H, *w2H, *lwH;
    cudaGetSymbolAddress((void**)&xres, g_xres);
    cudaGetSymbolAddress((void**)&xn,   g_xn16);
    cudaGetSymbolAddress((void**)&xe,   g_xe16);
    cudaGetSymbolAddress((void**)&hT,   g_hT16);
    cudaGetSymbolAddress((void**)&u1T,  g_u1T16);
    cudaGetSymbolAddress((void**)&r,    g_r16);
    cudaGetSymbolAddress((void**)&mlp,  g_mlp16);
    cudaGetSymbolAddress((void**)&gwH,  g_gwH);
    cudaGetSymbolAddress((void**)&gwTH, g_gwTH);
    cudaGetSymbolAddress((void**)&ewH,  g_ewH);
    cudaGetSymbolAddress((void**)&owH,  g_owH);
    cudaGetSymbolAddress((void**)&w1H,  g_w1H);
    cudaGetSymbolAddress((void**)&w2H,  g_w2H);
    cudaGetSymbolAddress((void**)&lwH,  g_lwH);

    cudaFuncSetAttribute(mma_gemm<0>, cudaFuncAttributeMaxDynamicSharedMemorySize, MM_SMEM);
    cudaFuncSetAttribute(mma_gemm<1>, cudaFuncAttributeMaxDynamicSharedMemorySize, MM_SMEM);
    cudaFuncSetAttribute(mma_gemm<2>, cudaFuncAttributeMaxDynamicSharedMemorySize, MM_SMEM);
    cudaFuncSetAttribute(mma_gemm<4>, cudaFuncAttributeMaxDynamicSharedMemorySize, MM_SMEM);
    cudaFuncSetAttribute(mma_gemm<5>, cudaFuncAttributeMaxDynamicSharedMemorySize, MM_SMEM);
    cudaFuncSetAttribute(mma_gemm<6>, cudaFuncAttributeMaxDynamicSharedMemorySize, MM_SMEM);

    const long long SB = 512LL * 256;
    const long long SC = 256LL * 512;

    prep_kernel<<<19076, 256>>>(ew, ow, w1, w2, gw, lw, h0,
                                ewH, owH, w1H, w2H, gwH, lwH, gwTH, hT);
    ln_kernel<<<BSROWS / 8, 256>>>(x, ln1g, ln1b, xn);
    mma_gemm<0><<<dim3(4, 256, 1), 512, MM_SMEM>>>(xn, ewH, eb, nullptr, xe, nullptr, 512, 512, 0, 0);

    for (int it = 0; it < 10; it++) {
        if (it < 9) {
            mma_gemm<5><<<dim3(4, 2, 128), 512, MM_SMEM>>>(gwTH, hT, lwH, xe, r, u1T, 256, 512, SB, SC);
            mma_gemm<4><<<dim3(4, 2, 128), 512, MM_SMEM>>>(gwH, u1T, nullptr, hT, hT, hT, 256, 512, SB, SC);
        } else {
            mma_gemm<6><<<dim3(4, 2, 128), 512, MM_SMEM>>>(gwTH, hT, lwH, xe, r, u1T, 256, 512, SB, SC);
        }
    }

    mma_gemm<1><<<dim3(4, 256, 1), 512, MM_SMEM>>>(r, owH, ob, x, xres, nullptr, 512, 512, 0, 0);
    ln_kernel<<<BSROWS / 8, 256>>>(xres, ln2g, ln2b, xn);
    mma_gemm<2><<<dim3(16, 256, 1), 512, MM_SMEM>>>(xn, w1H, b1, nullptr, mlp, nullptr, 512, 2048, 0, 0);
    mma_gemm<1><<<dim3(4, 256, 1), 512, MM_SMEM>>>(mlp, w2H, b2, xres, out, nullptr, 2048, 512, 0, 0);
}